// round 4
// baseline (speedup 1.0000x reference)
#include <cuda_runtime.h>

#define NNODES 50000
#define XROW   272      // IN_CH + POS_DIM
#define INC    256
#define HC     256      // HEADS * OUT_CH
#define NH     4
#define E0     500000
#define ET     550000   // edges + self loops

// ---------------- scratch (static device globals; no allocation) ----------------
__device__ __align__(16) float    g_content[(size_t)NNODES * HC]; // 51.2 MB
__device__ __align__(16) float    g_s[NNODES * NH];               // a_src + p_src
__device__ __align__(16) float    g_dv[NNODES * NH];              // a_dst + p_dst
__device__ __align__(16) unsigned g_amax[NNODES * NH];            // monotone float keys
__device__ __align__(16) float    g_denom[NNODES * NH];
__device__ __align__(16) float4   g_alpha[ET];                    // 8.8 MB
__device__             float      g_S[16];                        // pairwise alpha sums (10 used)

// ---------------- helpers ----------------
__device__ __forceinline__ unsigned fkey(float f) {
    unsigned u = __float_as_uint(f);
    return (u & 0x80000000u) ? ~u : (u | 0x80000000u);
}
__device__ __forceinline__ float funkey(unsigned k) {
    return (k & 0x80000000u) ? __uint_as_float(k ^ 0x80000000u) : __uint_as_float(~k);
}
__device__ __forceinline__ void red_add_v4(float* p, float a, float b, float c, float d) {
    asm volatile("red.global.add.v4.f32 [%0], {%1,%2,%3,%4};"
                 :: "l"(p), "f"(a), "f"(b), "f"(c), "f"(d) : "memory");
}

// ---------------- K1: content = x[:, :256] @ lin_w.T  (fp32 tiled) ----------------
__global__ void __launch_bounds__(256) k_gemm(const float* __restrict__ x,
                                              const float* __restrict__ w) {
    __shared__ float xs[64][17];
    __shared__ float ws[16][256];
    const int n0 = blockIdx.x * 64;
    const int t  = threadIdx.x;
    const int ty = t >> 4, tx = t & 15;

    float acc[4][16];
#pragma unroll
    for (int i = 0; i < 4; i++)
#pragma unroll
        for (int j = 0; j < 16; j++) acc[i][j] = 0.f;

    const int lr = t >> 2;            // 0..63
    const int lk = (t & 3) * 4;       // 0,4,8,12
    const float4* wrow = reinterpret_cast<const float4*>(w + (size_t)t * INC);

    for (int k0 = 0; k0 < INC; k0 += 16) {
        float4 xv = make_float4(0.f, 0.f, 0.f, 0.f);
        const int n = n0 + lr;
        if (n < NNODES)
            xv = *reinterpret_cast<const float4*>(x + (size_t)n * XROW + k0 + lk);
        xs[lr][lk + 0] = xv.x; xs[lr][lk + 1] = xv.y;
        xs[lr][lk + 2] = xv.z; xs[lr][lk + 3] = xv.w;

        float4 w0 = wrow[(k0 >> 2) + 0];
        float4 w1 = wrow[(k0 >> 2) + 1];
        float4 w2 = wrow[(k0 >> 2) + 2];
        float4 w3 = wrow[(k0 >> 2) + 3];
        ws[ 0][t] = w0.x; ws[ 1][t] = w0.y; ws[ 2][t] = w0.z; ws[ 3][t] = w0.w;
        ws[ 4][t] = w1.x; ws[ 5][t] = w1.y; ws[ 6][t] = w1.z; ws[ 7][t] = w1.w;
        ws[ 8][t] = w2.x; ws[ 9][t] = w2.y; ws[10][t] = w2.z; ws[11][t] = w2.w;
        ws[12][t] = w3.x; ws[13][t] = w3.y; ws[14][t] = w3.z; ws[15][t] = w3.w;
        __syncthreads();

#pragma unroll
        for (int kt = 0; kt < 16; kt++) {
            const float a0 = xs[ty * 4 + 0][kt];
            const float a1 = xs[ty * 4 + 1][kt];
            const float a2 = xs[ty * 4 + 2][kt];
            const float a3 = xs[ty * 4 + 3][kt];
#pragma unroll
            for (int j = 0; j < 16; j++) {
                const float b = ws[kt][tx + (j << 4)];
                acc[0][j] = fmaf(a0, b, acc[0][j]);
                acc[1][j] = fmaf(a1, b, acc[1][j]);
                acc[2][j] = fmaf(a2, b, acc[2][j]);
                acc[3][j] = fmaf(a3, b, acc[3][j]);
            }
        }
        __syncthreads();
    }

#pragma unroll
    for (int i = 0; i < 4; i++) {
        const int n = n0 + ty * 4 + i;
        if (n < NNODES) {
#pragma unroll
            for (int j = 0; j < 16; j++)
                g_content[(size_t)n * HC + tx + (j << 4)] = acc[i][j];
        }
    }
}

// ---------------- K2: per-node attention logits; init amax/denom ----------------
__global__ void __launch_bounds__(256) k_nodeatt(const float* __restrict__ x,
                                                 const float* __restrict__ att,
                                                 const float* __restrict__ patt) {
    const int gw   = (blockIdx.x * blockDim.x + threadIdx.x) >> 5;
    const int lane = threadIdx.x & 31;
    if (gw >= NNODES) return;
    const float* cont = g_content + (size_t)gw * HC;
    const float* pos  = x + (size_t)gw * XROW + INC;
    const float pv = (lane < 16) ? pos[lane] : 0.f;
#pragma unroll
    for (int h = 0; h < NH; h++) {
        const float c0 = cont[h * 64 + lane];
        const float c1 = cont[h * 64 + 32 + lane];
        float vs = c0 * att[h * 128 + lane]      + c1 * att[h * 128 + 32 + lane];
        float vd = c0 * att[h * 128 + 64 + lane] + c1 * att[h * 128 + 96 + lane];
        if (lane < 16) {
            vs += pv * patt[h * 32 + lane];
            vd += pv * patt[h * 32 + 16 + lane];
        }
#pragma unroll
        for (int o = 16; o > 0; o >>= 1) {
            vs += __shfl_xor_sync(0xffffffffu, vs, o);
            vd += __shfl_xor_sync(0xffffffffu, vd, o);
        }
        if (lane == 0) { g_s[gw * NH + h] = vs; g_dv[gw * NH + h] = vd; }
    }
    if (lane < NH) { g_amax[gw * NH + lane] = 0u; g_denom[gw * NH + lane] = 0.f; }
}

// ---------------- K3: out = bias (broadcast), zero pair sums ----------------
__global__ void k_init_out(float* __restrict__ out, const float* __restrict__ bias, int outn) {
    const int i = blockIdx.x * blockDim.x + threadIdx.x;
    if (i < 16) g_S[i] = 0.f;
    if (i < outn) out[i] = bias[i & (HC - 1)];
}

// ---------------- K4: edge logits + leaky relu + segment max ----------------
__global__ void __launch_bounds__(256) k_logits(const int* __restrict__ ei) {
    const int e = blockIdx.x * blockDim.x + threadIdx.x;
    if (e >= ET) return;
    int r, c;
    if (e < E0) { r = ei[e]; c = ei[E0 + e]; } else { r = c = e - E0; }
    const float4 sv = *reinterpret_cast<const float4*>(g_s  + r * NH);
    const float4 dv = *reinterpret_cast<const float4*>(g_dv + c * NH);
    float a0 = sv.x + dv.x, a1 = sv.y + dv.y, a2 = sv.z + dv.z, a3 = sv.w + dv.w;
    a0 = a0 > 0.f ? a0 : 0.2f * a0;
    a1 = a1 > 0.f ? a1 : 0.2f * a1;
    a2 = a2 > 0.f ? a2 : 0.2f * a2;
    a3 = a3 > 0.f ? a3 : 0.2f * a3;
    g_alpha[e] = make_float4(a0, a1, a2, a3);
    atomicMax(&g_amax[r * NH + 0], fkey(a0));
    atomicMax(&g_amax[r * NH + 1], fkey(a1));
    atomicMax(&g_amax[r * NH + 2], fkey(a2));
    atomicMax(&g_amax[r * NH + 3], fkey(a3));
}

// ---------------- K5: exp(alpha - max) + segment sum ----------------
__global__ void __launch_bounds__(256) k_exp(const int* __restrict__ ei) {
    const int e = blockIdx.x * blockDim.x + threadIdx.x;
    if (e >= ET) return;
    const int r = (e < E0) ? ei[e] : e - E0;
    const float4 a  = g_alpha[e];
    const uint4  mk = *reinterpret_cast<const uint4*>(g_amax + r * NH);
    const float e0 = __expf(a.x - funkey(mk.x));
    const float e1 = __expf(a.y - funkey(mk.y));
    const float e2 = __expf(a.z - funkey(mk.z));
    const float e3 = __expf(a.w - funkey(mk.w));
    g_alpha[e] = make_float4(e0, e1, e2, e3);
    red_add_v4(g_denom + r * NH, e0, e1, e2, e3);
}

// ---------------- K6: normalize alpha + pairwise sums for diversity ----------------
__global__ void __launch_bounds__(256) k_norm(const int* __restrict__ ei) {
    __shared__ float red[8][10];
    const int e = blockIdx.x * 256 + threadIdx.x;
    float w0 = 0.f, w1 = 0.f, w2 = 0.f, w3 = 0.f;
    if (e < ET) {
        const int r = (e < E0) ? ei[e] : e - E0;
        const float4 a   = g_alpha[e];
        const float4 den = *reinterpret_cast<const float4*>(g_denom + r * NH);
        w0 = a.x / (den.x + 1e-16f);
        w1 = a.y / (den.y + 1e-16f);
        w2 = a.z / (den.z + 1e-16f);
        w3 = a.w / (den.w + 1e-16f);
        g_alpha[e] = make_float4(w0, w1, w2, w3);
    }
    // pairs: (0,0)(0,1)(0,2)(0,3)(1,1)(1,2)(1,3)(2,2)(2,3)(3,3)
    float p[10];
    p[0] = w0 * w0; p[1] = w0 * w1; p[2] = w0 * w2; p[3] = w0 * w3;
    p[4] = w1 * w1; p[5] = w1 * w2; p[6] = w1 * w3;
    p[7] = w2 * w2; p[8] = w2 * w3; p[9] = w3 * w3;
#pragma unroll
    for (int i = 0; i < 10; i++)
#pragma unroll
        for (int o = 16; o > 0; o >>= 1)
            p[i] += __shfl_xor_sync(0xffffffffu, p[i], o);
    const int wid = threadIdx.x >> 5, lane = threadIdx.x & 31;
    if (lane == 0) {
#pragma unroll
        for (int i = 0; i < 10; i++) red[wid][i] = p[i];
    }
    __syncthreads();
    if (threadIdx.x < 10) {
        float s = 0.f;
#pragma unroll
        for (int k = 0; k < 8; k++) s += red[k][threadIdx.x];
        atomicAdd(&g_S[threadIdx.x], s);
    }
}

// ---------------- K7: message aggregation (the big one) ----------------
// thread = (edge, 4-channel group); 64 threads per edge; v4 reductions to out
__global__ void __launch_bounds__(256) k_agg(const int* __restrict__ ei,
                                             float* __restrict__ out) {
    const int gid = blockIdx.x * 256 + threadIdx.x;
    const int e = gid >> 6;
    if (e >= ET) return;
    const int q = gid & 63;                 // channel quad 0..63, head = q>>4
    int r, c;
    if (e < E0) { r = ei[e]; c = ei[E0 + e]; } else { r = c = e - E0; }
    const float wv = reinterpret_cast<const float*>(g_alpha)[e * 4 + (q >> 4)];
    const float4 v = *reinterpret_cast<const float4*>(g_content + (size_t)c * HC + q * 4);
    red_add_v4(out + (size_t)r * HC + q * 4, v.x * wv, v.y * wv, v.z * wv, v.w * wv);
}

// ---------------- K8: diversity scalar ----------------
__global__ void k_finish(float* __restrict__ out, int outn) {
    if (blockIdx.x == 0 && threadIdx.x == 0) {
        const float n0 = fmaxf(sqrtf(g_S[0]), 1e-8f);
        const float n1 = fmaxf(sqrtf(g_S[4]), 1e-8f);
        const float n2 = fmaxf(sqrtf(g_S[7]), 1e-8f);
        const float n3 = fmaxf(sqrtf(g_S[9]), 1e-8f);
        float s = 0.f;
        s += 2.f * g_S[1] / (n0 * n1);
        s += 2.f * g_S[2] / (n0 * n2);
        s += 2.f * g_S[3] / (n0 * n3);
        s += 2.f * g_S[5] / (n1 * n2);
        s += 2.f * g_S[6] / (n1 * n3);
        s += 2.f * g_S[8] / (n2 * n3);
        out[outn] = (s / 16.f) * 0.1f;
    }
}

// ---------------- launch ----------------
extern "C" void kernel_launch(void* const* d_in, const int* in_sizes, int n_in,
                              void* d_out, int out_size) {
    const float* x    = (const float*)d_in[0];
    const int*   ei   = (const int*)d_in[1];
    const float* w    = (const float*)d_in[2];
    const float* att  = (const float*)d_in[3];
    const float* patt = (const float*)d_in[4];
    const float* bias = (const float*)d_in[5];
    float* out = (float*)d_out;
    const int outn = out_size - 1;   // last element is the diversity scalar

    k_gemm    <<<(NNODES + 63) / 64, 256>>>(x, w);
    k_init_out<<<(outn + 255) / 256, 256>>>(out, bias, outn);
    k_nodeatt <<<(NNODES * 32 + 255) / 256, 256>>>(x, att, patt);
    k_logits  <<<(ET + 255) / 256, 256>>>(ei);
    k_exp     <<<(ET + 255) / 256, 256>>>(ei);
    k_norm    <<<(ET + 255) / 256, 256>>>(ei);
    k_agg     <<<(ET * 64) / 256, 256>>>(ei, out);
    k_finish  <<<1, 32>>>(out, outn);
}

// round 9
// speedup vs baseline: 1.4249x; 1.4249x over previous
#include <cuda_runtime.h>
#include <cuda_bf16.h>
#include <cstdint>

#define NNODES 50000
#define XROW   272      // IN_CH + POS_DIM
#define INC    256
#define HC     256      // HEADS * OUT_CH
#define NH     4
#define E0     500000
#define ET     550000   // edges + self loops

// ---- GEMM tiling ----
#define TILE_M 128
#define TILE_N 128
#define KCHUNK 64
#define SROW   144                       // smem row stride bytes (72 bf16) -> conflict-free frags
#define SM_AHI 0
#define SM_ALO (SM_AHI + TILE_M * SROW)  // 18432
#define SM_BHI (SM_ALO + TILE_M * SROW)  // 36864
#define SM_BLO (SM_BHI + TILE_N * SROW)  // 55296
#define SM_TOT (SM_BLO + TILE_N * SROW)  // 73728

// ---------------- scratch (static device globals; no allocation) ----------------
__device__ __align__(16) float          g_content[(size_t)NNODES * HC]; // 51.2 MB
__device__ __align__(16) __nv_bfloat16  g_whi[INC * HC];                // split W hi
__device__ __align__(16) __nv_bfloat16  g_wlo[INC * HC];                // split W lo
__device__ __align__(16) float    g_s[NNODES * NH];
__device__ __align__(16) float    g_dv[NNODES * NH];
__device__ __align__(16) unsigned g_amax[NNODES * NH];
__device__ __align__(16) float    g_denom[NNODES * NH];
__device__ __align__(16) float4   g_alpha[ET];
__device__             float      g_S[16];

// ---------------- helpers ----------------
__device__ __forceinline__ unsigned fkey(float f) {
    unsigned u = __float_as_uint(f);
    return (u & 0x80000000u) ? ~u : (u | 0x80000000u);
}
__device__ __forceinline__ float funkey(unsigned k) {
    return (k & 0x80000000u) ? __uint_as_float(k ^ 0x80000000u) : __uint_as_float(~k);
}
__device__ __forceinline__ void red_add_v4(float* p, float a, float b, float c, float d) {
    asm volatile("red.global.add.v4.f32 [%0], {%1,%2,%3,%4};"
                 :: "l"(p), "f"(a), "f"(b), "f"(c), "f"(d) : "memory");
}
// pack 8 floats -> 8 bf16 (hi) + 8 bf16 (lo residual)
__device__ __forceinline__ void split8(const float* f, uint4& hi, uint4& lo) {
    float r[8];
    __nv_bfloat162 h01 = __floats2bfloat162_rn(f[0], f[1]);
    __nv_bfloat162 h23 = __floats2bfloat162_rn(f[2], f[3]);
    __nv_bfloat162 h45 = __floats2bfloat162_rn(f[4], f[5]);
    __nv_bfloat162 h67 = __floats2bfloat162_rn(f[6], f[7]);
    r[0] = f[0] - __bfloat162float(h01.x); r[1] = f[1] - __bfloat162float(h01.y);
    r[2] = f[2] - __bfloat162float(h23.x); r[3] = f[3] - __bfloat162float(h23.y);
    r[4] = f[4] - __bfloat162float(h45.x); r[5] = f[5] - __bfloat162float(h45.y);
    r[6] = f[6] - __bfloat162float(h67.x); r[7] = f[7] - __bfloat162float(h67.y);
    __nv_bfloat162 l01 = __floats2bfloat162_rn(r[0], r[1]);
    __nv_bfloat162 l23 = __floats2bfloat162_rn(r[2], r[3]);
    __nv_bfloat162 l45 = __floats2bfloat162_rn(r[4], r[5]);
    __nv_bfloat162 l67 = __floats2bfloat162_rn(r[6], r[7]);
    hi.x = *(uint32_t*)&h01; hi.y = *(uint32_t*)&h23; hi.z = *(uint32_t*)&h45; hi.w = *(uint32_t*)&h67;
    lo.x = *(uint32_t*)&l01; lo.y = *(uint32_t*)&l23; lo.z = *(uint32_t*)&l45; lo.w = *(uint32_t*)&l67;
}
__device__ __forceinline__ void mma16816(float* d, const uint32_t* a, const uint32_t* b) {
    asm volatile(
        "mma.sync.aligned.m16n8k16.row.col.f32.bf16.bf16.f32 "
        "{%0,%1,%2,%3}, {%4,%5,%6,%7}, {%8,%9}, {%0,%1,%2,%3};"
        : "+f"(d[0]), "+f"(d[1]), "+f"(d[2]), "+f"(d[3])
        : "r"(a[0]), "r"(a[1]), "r"(a[2]), "r"(a[3]), "r"(b[0]), "r"(b[1]));
}

// ---------------- K0: split W into bf16 hi/lo planes ----------------
__global__ void k_wsplit(const float* __restrict__ w) {
    const int i = blockIdx.x * blockDim.x + threadIdx.x;
    if (i < INC * HC) {
        const float v = w[i];
        const __nv_bfloat16 h = __float2bfloat16_rn(v);
        g_whi[i] = h;
        g_wlo[i] = __float2bfloat16_rn(v - __bfloat162float(h));
    }
}

// ---------------- K1: content = x[:, :256] @ lin_w.T  (HMMA split-bf16) ----------------
__global__ void __launch_bounds__(256) k_gemm(const float* __restrict__ x) {
    extern __shared__ char sm[];
    const int tid  = threadIdx.x;
    const int wid  = tid >> 5;
    const int lane = tid & 31;
    const int m0   = blockIdx.x * TILE_M;
    const int nb   = blockIdx.y * TILE_N;
    const int mo   = (wid >> 1) * 32;      // warp M offset in tile
    const int no   = (wid & 1) * 64;       // warp N offset in tile
    const int g    = lane >> 2;            // fragment group row 0..7
    const int c    = lane & 3;             // fragment col pair 0..3

    float acc[2][8][4];
#pragma unroll
    for (int mi = 0; mi < 2; mi++)
#pragma unroll
        for (int ni = 0; ni < 8; ni++)
#pragma unroll
            for (int q = 0; q < 4; q++) acc[mi][ni][q] = 0.f;

    for (int ch = 0; ch < INC / KCHUNK; ch++) {
        const int k0 = ch * KCHUNK;

        // ---- A: load x chunk (fp32), split -> smem hi/lo ----
        {
            const int r = tid >> 1;              // 0..127
            const int h = (tid & 1) * 32;        // col half
            const int n = m0 + r;
            float f[32];
            if (n < NNODES) {
                const float4* p = reinterpret_cast<const float4*>(x + (size_t)n * XROW + k0 + h);
#pragma unroll
                for (int j = 0; j < 8; j++) {
                    float4 v = p[j];
                    f[j * 4 + 0] = v.x; f[j * 4 + 1] = v.y; f[j * 4 + 2] = v.z; f[j * 4 + 3] = v.w;
                }
            } else {
#pragma unroll
                for (int j = 0; j < 32; j++) f[j] = 0.f;
            }
#pragma unroll
            for (int g4 = 0; g4 < 4; g4++) {
                uint4 hi, lo;
                split8(f + g4 * 8, hi, lo);
                const int off = r * SROW + (h + g4 * 8) * 2;
                *reinterpret_cast<uint4*>(sm + SM_AHI + off) = hi;
                *reinterpret_cast<uint4*>(sm + SM_ALO + off) = lo;
            }
        }
        // ---- B: copy pre-split W chunk -> smem hi/lo ----
        {
            const int r = tid >> 1;
            const int h = (tid & 1) * 32;
            const uint4* ph = reinterpret_cast<const uint4*>(g_whi + (size_t)(nb + r) * INC + k0 + h);
            const uint4* pl = reinterpret_cast<const uint4*>(g_wlo + (size_t)(nb + r) * INC + k0 + h);
            const int off = r * SROW + h * 2;
#pragma unroll
            for (int j = 0; j < 4; j++) {        // 4 x 8 bf16 = 32 bf16
                *reinterpret_cast<uint4*>(sm + SM_BHI + off + j * 16) = ph[j];
                *reinterpret_cast<uint4*>(sm + SM_BLO + off + j * 16) = pl[j];
            }
        }
        __syncthreads();

        // ---- compute: 4 k16 steps ----
#pragma unroll
        for (int ks = 0; ks < 4; ks++) {
            const int kb = ks * 32 + c * 4;      // byte offset of this lane's k pair
            uint32_t ah[2][4], al[2][4];
#pragma unroll
            for (int mi = 0; mi < 2; mi++) {
                const int base = (mo + mi * 16 + g) * SROW + kb;
                ah[mi][0] = *reinterpret_cast<const uint32_t*>(sm + SM_AHI + base);
                ah[mi][1] = *reinterpret_cast<const uint32_t*>(sm + SM_AHI + base + 8 * SROW);
                ah[mi][2] = *reinterpret_cast<const uint32_t*>(sm + SM_AHI + base + 16);
                ah[mi][3] = *reinterpret_cast<const uint32_t*>(sm + SM_AHI + base + 8 * SROW + 16);
                al[mi][0] = *reinterpret_cast<const uint32_t*>(sm + SM_ALO + base);
                al[mi][1] = *reinterpret_cast<const uint32_t*>(sm + SM_ALO + base + 8 * SROW);
                al[mi][2] = *reinterpret_cast<const uint32_t*>(sm + SM_ALO + base + 16);
                al[mi][3] = *reinterpret_cast<const uint32_t*>(sm + SM_ALO + base + 8 * SROW + 16);
            }
#pragma unroll
            for (int ni = 0; ni < 8; ni++) {
                const int bbase = (no + ni * 8 + g) * SROW + kb;
                uint32_t bh[2], bl[2];
                bh[0] = *reinterpret_cast<const uint32_t*>(sm + SM_BHI + bbase);
                bh[1] = *reinterpret_cast<const uint32_t*>(sm + SM_BHI + bbase + 16);
                bl[0] = *reinterpret_cast<const uint32_t*>(sm + SM_BLO + bbase);
                bl[1] = *reinterpret_cast<const uint32_t*>(sm + SM_BLO + bbase + 16);
                mma16816(acc[0][ni], ah[0], bh);
                mma16816(acc[1][ni], ah[1], bh);
                mma16816(acc[0][ni], ah[0], bl);
                mma16816(acc[1][ni], ah[1], bl);
                mma16816(acc[0][ni], al[0], bh);
                mma16816(acc[1][ni], al[1], bh);
            }
        }
        __syncthreads();
    }

    // ---- epilogue: write 32x64 warp tile ----
#pragma unroll
    for (int mi = 0; mi < 2; mi++) {
        const int r0 = m0 + mo + mi * 16 + g;
        const int r1 = r0 + 8;
#pragma unroll
        for (int ni = 0; ni < 8; ni++) {
            const int col = nb + no + ni * 8 + c * 2;
            if (r0 < NNODES)
                *reinterpret_cast<float2*>(g_content + (size_t)r0 * HC + col) =
                    make_float2(acc[mi][ni][0], acc[mi][ni][1]);
            if (r1 < NNODES)
                *reinterpret_cast<float2*>(g_content + (size_t)r1 * HC + col) =
                    make_float2(acc[mi][ni][2], acc[mi][ni][3]);
        }
    }
}

// ---------------- K2: per-node attention logits; init amax/denom ----------------
__global__ void __launch_bounds__(256) k_nodeatt(const float* __restrict__ x,
                                                 const float* __restrict__ att,
                                                 const float* __restrict__ patt) {
    const int gw   = (blockIdx.x * blockDim.x + threadIdx.x) >> 5;
    const int lane = threadIdx.x & 31;
    if (gw >= NNODES) return;
    const float* cont = g_content + (size_t)gw * HC;
    const float* pos  = x + (size_t)gw * XROW + INC;
    const float pv = (lane < 16) ? pos[lane] : 0.f;
#pragma unroll
    for (int h = 0; h < NH; h++) {
        const float c0 = cont[h * 64 + lane];
        const float c1 = cont[h * 64 + 32 + lane];
        float vs = c0 * att[h * 128 + lane]      + c1 * att[h * 128 + 32 + lane];
        float vd = c0 * att[h * 128 + 64 + lane] + c1 * att[h * 128 + 96 + lane];
        if (lane < 16) {
            vs += pv * patt[h * 32 + lane];
            vd += pv * patt[h * 32 + 16 + lane];
        }
#pragma unroll
        for (int o = 16; o > 0; o >>= 1) {
            vs += __shfl_xor_sync(0xffffffffu, vs, o);
            vd += __shfl_xor_sync(0xffffffffu, vd, o);
        }
        if (lane == 0) { g_s[gw * NH + h] = vs; g_dv[gw * NH + h] = vd; }
    }
    if (lane < NH) { g_amax[gw * NH + lane] = 0u; g_denom[gw * NH + lane] = 0.f; }
}

// ---------------- K3: out = bias (broadcast), zero pair sums ----------------
__global__ void k_init_out(float* __restrict__ out, const float* __restrict__ bias, int outn) {
    const int i = blockIdx.x * blockDim.x + threadIdx.x;
    if (i < 16) g_S[i] = 0.f;
    if (i < outn) out[i] = bias[i & (HC - 1)];
}

// ---------------- K4: edge logits + leaky relu + segment max ----------------
__global__ void __launch_bounds__(256) k_logits(const int* __restrict__ ei) {
    const int e = blockIdx.x * blockDim.x + threadIdx.x;
    if (e >= ET) return;
    int r, c;
    if (e < E0) { r = ei[e]; c = ei[E0 + e]; } else { r = c = e - E0; }
    const float4 sv = *reinterpret_cast<const float4*>(g_s  + r * NH);
    const float4 dv = *reinterpret_cast<const float4*>(g_dv + c * NH);
    float a0 = sv.x + dv.x, a1 = sv.y + dv.y, a2 = sv.z + dv.z, a3 = sv.w + dv.w;
    a0 = a0 > 0.f ? a0 : 0.2f * a0;
    a1 = a1 > 0.f ? a1 : 0.2f * a1;
    a2 = a2 > 0.f ? a2 : 0.2f * a2;
    a3 = a3 > 0.f ? a3 : 0.2f * a3;
    g_alpha[e] = make_float4(a0, a1, a2, a3);
    atomicMax(&g_amax[r * NH + 0], fkey(a0));
    atomicMax(&g_amax[r * NH + 1], fkey(a1));
    atomicMax(&g_amax[r * NH + 2], fkey(a2));
    atomicMax(&g_amax[r * NH + 3], fkey(a3));
}

// ---------------- K5: exp(alpha - max) + segment sum ----------------
__global__ void __launch_bounds__(256) k_exp(const int* __restrict__ ei) {
    const int e = blockIdx.x * blockDim.x + threadIdx.x;
    if (e >= ET) return;
    const int r = (e < E0) ? ei[e] : e - E0;
    const float4 a  = g_alpha[e];
    const uint4  mk = *reinterpret_cast<const uint4*>(g_amax + r * NH);
    const float e0 = __expf(a.x - funkey(mk.x));
    const float e1 = __expf(a.y - funkey(mk.y));
    const float e2 = __expf(a.z - funkey(mk.z));
    const float e3 = __expf(a.w - funkey(mk.w));
    g_alpha[e] = make_float4(e0, e1, e2, e3);
    red_add_v4(g_denom + r * NH, e0, e1, e2, e3);
}

// ---------------- K6: normalize alpha + pairwise sums for diversity ----------------
__global__ void __launch_bounds__(256) k_norm(const int* __restrict__ ei) {
    __shared__ float red[8][10];
    const int e = blockIdx.x * 256 + threadIdx.x;
    float w0 = 0.f, w1 = 0.f, w2 = 0.f, w3 = 0.f;
    if (e < ET) {
        const int r = (e < E0) ? ei[e] : e - E0;
        const float4 a   = g_alpha[e];
        const float4 den = *reinterpret_cast<const float4*>(g_denom + r * NH);
        w0 = a.x / (den.x + 1e-16f);
        w1 = a.y / (den.y + 1e-16f);
        w2 = a.z / (den.z + 1e-16f);
        w3 = a.w / (den.w + 1e-16f);
        g_alpha[e] = make_float4(w0, w1, w2, w3);
    }
    float p[10];
    p[0] = w0 * w0; p[1] = w0 * w1; p[2] = w0 * w2; p[3] = w0 * w3;
    p[4] = w1 * w1; p[5] = w1 * w2; p[6] = w1 * w3;
    p[7] = w2 * w2; p[8] = w2 * w3; p[9] = w3 * w3;
#pragma unroll
    for (int i = 0; i < 10; i++)
#pragma unroll
        for (int o = 16; o > 0; o >>= 1)
            p[i] += __shfl_xor_sync(0xffffffffu, p[i], o);
    const int wid = threadIdx.x >> 5, lane = threadIdx.x & 31;
    if (lane == 0) {
#pragma unroll
        for (int i = 0; i < 10; i++) red[wid][i] = p[i];
    }
    __syncthreads();
    if (threadIdx.x < 10) {
        float s = 0.f;
#pragma unroll
        for (int k = 0; k < 8; k++) s += red[k][threadIdx.x];
        atomicAdd(&g_S[threadIdx.x], s);
    }
}

// ---------------- K7: message aggregation ----------------
__global__ void __launch_bounds__(256) k_agg(const int* __restrict__ ei,
                                             float* __restrict__ out) {
    const int gid = blockIdx.x * 256 + threadIdx.x;
    const int e = gid >> 6;
    if (e >= ET) return;
    const int q = gid & 63;
    int r, c;
    if (e < E0) { r = ei[e]; c = ei[E0 + e]; } else { r = c = e - E0; }
    const float wv = reinterpret_cast<const float*>(g_alpha)[e * 4 + (q >> 4)];
    const float4 v = *reinterpret_cast<const float4*>(g_content + (size_t)c * HC + q * 4);
    red_add_v4(out + (size_t)r * HC + q * 4, v.x * wv, v.y * wv, v.z * wv, v.w * wv);
}

// ---------------- K8: diversity scalar ----------------
__global__ void k_finish(float* __restrict__ out, int outn) {
    if (blockIdx.x == 0 && threadIdx.x == 0) {
        const float n0 = fmaxf(sqrtf(g_S[0]), 1e-8f);
        const float n1 = fmaxf(sqrtf(g_S[4]), 1e-8f);
        const float n2 = fmaxf(sqrtf(g_S[7]), 1e-8f);
        const float n3 = fmaxf(sqrtf(g_S[9]), 1e-8f);
        float s = 0.f;
        s += 2.f * g_S[1] / (n0 * n1);
        s += 2.f * g_S[2] / (n0 * n2);
        s += 2.f * g_S[3] / (n0 * n3);
        s += 2.f * g_S[5] / (n1 * n2);
        s += 2.f * g_S[6] / (n1 * n3);
        s += 2.f * g_S[8] / (n2 * n3);
        out[outn] = (s / 16.f) * 0.1f;
    }
}

// ---------------- launch ----------------
extern "C" void kernel_launch(void* const* d_in, const int* in_sizes, int n_in,
                              void* d_out, int out_size) {
    const float* x    = (const float*)d_in[0];
    const int*   ei   = (const int*)d_in[1];
    const float* w    = (const float*)d_in[2];
    const float* att  = (const float*)d_in[3];
    const float* patt = (const float*)d_in[4];
    const float* bias = (const float*)d_in[5];
    float* out = (float*)d_out;
    const int outn = out_size - 1;

    static int smem_set = 0;
    if (!smem_set) {
        cudaFuncSetAttribute(k_gemm, cudaFuncAttributeMaxDynamicSharedMemorySize, SM_TOT);
        smem_set = 1;
    }

    dim3 ggrid((NNODES + TILE_M - 1) / TILE_M, HC / TILE_N);

    k_wsplit  <<<(INC * HC + 255) / 256, 256>>>(w);
    k_gemm    <<<ggrid, 256, SM_TOT>>>(x);
    k_init_out<<<(outn + 255) / 256, 256>>>(out, bias, outn);
    k_nodeatt <<<(NNODES * 32 + 255) / 256, 256>>>(x, att, patt);
    k_logits  <<<(ET + 255) / 256, 256>>>(ei);
    k_exp     <<<(ET + 255) / 256, 256>>>(ei);
    k_norm    <<<(ET + 255) / 256, 256>>>(ei);
    k_agg     <<<(ET * 64) / 256, 256>>>(ei, out);
    k_finish  <<<1, 32>>>(out, outn);
}

// round 10
// speedup vs baseline: 1.7225x; 1.2089x over previous
#include <cuda_runtime.h>
#include <cuda_bf16.h>
#include <cstdint>

#define NNODES 50000
#define XROW   272      // IN_CH + POS_DIM
#define INC    256
#define HC     256      // HEADS * OUT_CH
#define NH     4
#define E0     500000
#define ET     550000   // edges + self loops

// ---- GEMM tiling ----
#define TILE_M 128
#define TILE_N 128
#define KCHUNK 64
#define SROW   144
#define SM_AHI 0
#define SM_ALO (SM_AHI + TILE_M * SROW)
#define SM_BHI (SM_ALO + TILE_M * SROW)
#define SM_BLO (SM_BHI + TILE_N * SROW)
#define SM_TOT (SM_BLO + TILE_N * SROW)   // 73728

// ---------------- scratch (static device globals; no allocation) ----------------
__device__ __align__(16) float          g_content[(size_t)NNODES * HC]; // 51.2 MB
__device__ __align__(16) __nv_bfloat16  g_whi[INC * HC];
__device__ __align__(16) __nv_bfloat16  g_wlo[INC * HC];
__device__ __align__(16) float    g_s[NNODES * NH];
__device__ __align__(16) float    g_dv[NNODES * NH];
__device__ __align__(16) float    g_denom[NNODES * NH];
__device__ __align__(16) float4   g_alpha[ET];          // exp(logit)
__device__ __align__(16) float4   g_salpha[ET];         // normalized, dest-sorted
__device__             int        g_scol[ET];           // col index, dest-sorted
__device__             int        g_count[NNODES];
__device__             int        g_rowptr[NNODES + 1];
__device__             int        g_cursor[NNODES];
__device__             float      g_S[16];

// ---------------- helpers ----------------
__device__ __forceinline__ void red_add_v4(float* p, float a, float b, float c, float d) {
    asm volatile("red.global.add.v4.f32 [%0], {%1,%2,%3,%4};"
                 :: "l"(p), "f"(a), "f"(b), "f"(c), "f"(d) : "memory");
}
__device__ __forceinline__ void split8(const float* f, uint4& hi, uint4& lo) {
    float r[8];
    __nv_bfloat162 h01 = __floats2bfloat162_rn(f[0], f[1]);
    __nv_bfloat162 h23 = __floats2bfloat162_rn(f[2], f[3]);
    __nv_bfloat162 h45 = __floats2bfloat162_rn(f[4], f[5]);
    __nv_bfloat162 h67 = __floats2bfloat162_rn(f[6], f[7]);
    r[0] = f[0] - __bfloat162float(h01.x); r[1] = f[1] - __bfloat162float(h01.y);
    r[2] = f[2] - __bfloat162float(h23.x); r[3] = f[3] - __bfloat162float(h23.y);
    r[4] = f[4] - __bfloat162float(h45.x); r[5] = f[5] - __bfloat162float(h45.y);
    r[6] = f[6] - __bfloat162float(h67.x); r[7] = f[7] - __bfloat162float(h67.y);
    __nv_bfloat162 l01 = __floats2bfloat162_rn(r[0], r[1]);
    __nv_bfloat162 l23 = __floats2bfloat162_rn(r[2], r[3]);
    __nv_bfloat162 l45 = __floats2bfloat162_rn(r[4], r[5]);
    __nv_bfloat162 l67 = __floats2bfloat162_rn(r[6], r[7]);
    hi.x = *(uint32_t*)&h01; hi.y = *(uint32_t*)&h23; hi.z = *(uint32_t*)&h45; hi.w = *(uint32_t*)&h67;
    lo.x = *(uint32_t*)&l01; lo.y = *(uint32_t*)&l23; lo.z = *(uint32_t*)&l45; lo.w = *(uint32_t*)&l67;
}
__device__ __forceinline__ void mma16816(float* d, const uint32_t* a, const uint32_t* b) {
    asm volatile(
        "mma.sync.aligned.m16n8k16.row.col.f32.bf16.bf16.f32 "
        "{%0,%1,%2,%3}, {%4,%5,%6,%7}, {%8,%9}, {%0,%1,%2,%3};"
        : "+f"(d[0]), "+f"(d[1]), "+f"(d[2]), "+f"(d[3])
        : "r"(a[0]), "r"(a[1]), "r"(a[2]), "r"(a[3]), "r"(b[0]), "r"(b[1]));
}

// ---------------- K0: split W into bf16 hi/lo planes ----------------
__global__ void k_wsplit(const float* __restrict__ w) {
    const int i = blockIdx.x * blockDim.x + threadIdx.x;
    if (i < INC * HC) {
        const float v = w[i];
        const __nv_bfloat16 h = __float2bfloat16_rn(v);
        g_whi[i] = h;
        g_wlo[i] = __float2bfloat16_rn(v - __bfloat162float(h));
    }
}

// ---------------- K1: content = x[:, :256] @ lin_w.T  (HMMA split-bf16) ----------------
__global__ void __launch_bounds__(256) k_gemm(const float* __restrict__ x) {
    extern __shared__ char sm[];
    const int tid  = threadIdx.x;
    const int wid  = tid >> 5;
    const int lane = tid & 31;
    const int m0   = blockIdx.x * TILE_M;
    const int nb   = blockIdx.y * TILE_N;
    const int mo   = (wid >> 1) * 32;
    const int no   = (wid & 1) * 64;
    const int g    = lane >> 2;
    const int c    = lane & 3;

    float acc[2][8][4];
#pragma unroll
    for (int mi = 0; mi < 2; mi++)
#pragma unroll
        for (int ni = 0; ni < 8; ni++)
#pragma unroll
            for (int q = 0; q < 4; q++) acc[mi][ni][q] = 0.f;

    for (int ch = 0; ch < INC / KCHUNK; ch++) {
        const int k0 = ch * KCHUNK;
        {
            const int r = tid >> 1;
            const int h = (tid & 1) * 32;
            const int n = m0 + r;
            float f[32];
            if (n < NNODES) {
                const float4* p = reinterpret_cast<const float4*>(x + (size_t)n * XROW + k0 + h);
#pragma unroll
                for (int j = 0; j < 8; j++) {
                    float4 v = p[j];
                    f[j * 4 + 0] = v.x; f[j * 4 + 1] = v.y; f[j * 4 + 2] = v.z; f[j * 4 + 3] = v.w;
                }
            } else {
#pragma unroll
                for (int j = 0; j < 32; j++) f[j] = 0.f;
            }
#pragma unroll
            for (int g4 = 0; g4 < 4; g4++) {
                uint4 hi, lo;
                split8(f + g4 * 8, hi, lo);
                const int off = r * SROW + (h + g4 * 8) * 2;
                *reinterpret_cast<uint4*>(sm + SM_AHI + off) = hi;
                *reinterpret_cast<uint4*>(sm + SM_ALO + off) = lo;
            }
        }
        {
            const int r = tid >> 1;
            const int h = (tid & 1) * 32;
            const uint4* ph = reinterpret_cast<const uint4*>(g_whi + (size_t)(nb + r) * INC + k0 + h);
            const uint4* pl = reinterpret_cast<const uint4*>(g_wlo + (size_t)(nb + r) * INC + k0 + h);
            const int off = r * SROW + h * 2;
#pragma unroll
            for (int j = 0; j < 4; j++) {
                *reinterpret_cast<uint4*>(sm + SM_BHI + off + j * 16) = ph[j];
                *reinterpret_cast<uint4*>(sm + SM_BLO + off + j * 16) = pl[j];
            }
        }
        __syncthreads();

#pragma unroll
        for (int ks = 0; ks < 4; ks++) {
            const int kb = ks * 32 + c * 4;
            uint32_t ah[2][4], al[2][4];
#pragma unroll
            for (int mi = 0; mi < 2; mi++) {
                const int base = (mo + mi * 16 + g) * SROW + kb;
                ah[mi][0] = *reinterpret_cast<const uint32_t*>(sm + SM_AHI + base);
                ah[mi][1] = *reinterpret_cast<const uint32_t*>(sm + SM_AHI + base + 8 * SROW);
                ah[mi][2] = *reinterpret_cast<const uint32_t*>(sm + SM_AHI + base + 16);
                ah[mi][3] = *reinterpret_cast<const uint32_t*>(sm + SM_AHI + base + 8 * SROW + 16);
                al[mi][0] = *reinterpret_cast<const uint32_t*>(sm + SM_ALO + base);
                al[mi][1] = *reinterpret_cast<const uint32_t*>(sm + SM_ALO + base + 8 * SROW);
                al[mi][2] = *reinterpret_cast<const uint32_t*>(sm + SM_ALO + base + 16);
                al[mi][3] = *reinterpret_cast<const uint32_t*>(sm + SM_ALO + base + 8 * SROW + 16);
            }
#pragma unroll
            for (int ni = 0; ni < 8; ni++) {
                const int bbase = (no + ni * 8 + g) * SROW + kb;
                uint32_t bh[2], bl[2];
                bh[0] = *reinterpret_cast<const uint32_t*>(sm + SM_BHI + bbase);
                bh[1] = *reinterpret_cast<const uint32_t*>(sm + SM_BHI + bbase + 16);
                bl[0] = *reinterpret_cast<const uint32_t*>(sm + SM_BLO + bbase);
                bl[1] = *reinterpret_cast<const uint32_t*>(sm + SM_BLO + bbase + 16);
                mma16816(acc[0][ni], ah[0], bh);
                mma16816(acc[1][ni], ah[1], bh);
                mma16816(acc[0][ni], ah[0], bl);
                mma16816(acc[1][ni], ah[1], bl);
                mma16816(acc[0][ni], al[0], bh);
                mma16816(acc[1][ni], al[1], bh);
            }
        }
        __syncthreads();
    }

#pragma unroll
    for (int mi = 0; mi < 2; mi++) {
        const int r0 = m0 + mo + mi * 16 + g;
        const int r1 = r0 + 8;
#pragma unroll
        for (int ni = 0; ni < 8; ni++) {
            const int col = nb + no + ni * 8 + c * 2;
            if (r0 < NNODES)
                *reinterpret_cast<float2*>(g_content + (size_t)r0 * HC + col) =
                    make_float2(acc[mi][ni][0], acc[mi][ni][1]);
            if (r1 < NNODES)
                *reinterpret_cast<float2*>(g_content + (size_t)r1 * HC + col) =
                    make_float2(acc[mi][ni][2], acc[mi][ni][3]);
        }
    }
}

// ---------------- K2: per-node attention logits; zero denom + counts ----------------
__global__ void __launch_bounds__(256) k_nodeatt(const float* __restrict__ x,
                                                 const float* __restrict__ att,
                                                 const float* __restrict__ patt) {
    const int gw   = (blockIdx.x * blockDim.x + threadIdx.x) >> 5;
    const int lane = threadIdx.x & 31;
    if (gw >= NNODES) return;
    const float* cont = g_content + (size_t)gw * HC;
    const float* pos  = x + (size_t)gw * XROW + INC;
    const float pv = (lane < 16) ? pos[lane] : 0.f;
#pragma unroll
    for (int h = 0; h < NH; h++) {
        const float c0 = cont[h * 64 + lane];
        const float c1 = cont[h * 64 + 32 + lane];
        float vs = c0 * att[h * 128 + lane]      + c1 * att[h * 128 + 32 + lane];
        float vd = c0 * att[h * 128 + 64 + lane] + c1 * att[h * 128 + 96 + lane];
        if (lane < 16) {
            vs += pv * patt[h * 32 + lane];
            vd += pv * patt[h * 32 + 16 + lane];
        }
#pragma unroll
        for (int o = 16; o > 0; o >>= 1) {
            vs += __shfl_xor_sync(0xffffffffu, vs, o);
            vd += __shfl_xor_sync(0xffffffffu, vd, o);
        }
        if (lane == 0) { g_s[gw * NH + h] = vs; g_dv[gw * NH + h] = vd; }
    }
    if (lane < NH) g_denom[gw * NH + lane] = 0.f;
    if (lane == NH) g_count[gw] = 0;
}

// ---------------- K3: fused logits + leakyrelu + exp + denom + degree ----------------
// max-free softmax: logits are O(few sigma), exp() cannot overflow fp32
__global__ void __launch_bounds__(256) k_logexp(const int* __restrict__ ei) {
    const int e = blockIdx.x * blockDim.x + threadIdx.x;
    if (e >= ET) return;
    int r, c;
    if (e < E0) { r = ei[e]; c = ei[E0 + e]; } else { r = c = e - E0; }
    const float4 sv = *reinterpret_cast<const float4*>(g_s  + r * NH);
    const float4 dv = *reinterpret_cast<const float4*>(g_dv + c * NH);
    float a0 = sv.x + dv.x, a1 = sv.y + dv.y, a2 = sv.z + dv.z, a3 = sv.w + dv.w;
    a0 = a0 > 0.f ? a0 : 0.2f * a0;
    a1 = a1 > 0.f ? a1 : 0.2f * a1;
    a2 = a2 > 0.f ? a2 : 0.2f * a2;
    a3 = a3 > 0.f ? a3 : 0.2f * a3;
    const float e0 = __expf(a0), e1 = __expf(a1), e2 = __expf(a2), e3 = __expf(a3);
    g_alpha[e] = make_float4(e0, e1, e2, e3);
    red_add_v4(g_denom + r * NH, e0, e1, e2, e3);
    atomicAdd(&g_count[r], 1);
}

// ---------------- K4: single-block exclusive scan -> rowptr + cursor; zero g_S ----------------
#define SCAN_PER 49   // 1024 * 49 >= 50000
__global__ void __launch_bounds__(1024) k_scan() {
    __shared__ int sp[1024];
    const int t = threadIdx.x;
    const int base = t * SCAN_PER;
    int s = 0;
#pragma unroll 7
    for (int i = 0; i < SCAN_PER; i++) {
        const int idx = base + i;
        if (idx < NNODES) s += g_count[idx];
    }
    sp[t] = s;
    __syncthreads();
    for (int o = 1; o < 1024; o <<= 1) {
        const int v = (t >= o) ? sp[t - o] : 0;
        __syncthreads();
        sp[t] += v;
        __syncthreads();
    }
    int off = (t > 0) ? sp[t - 1] : 0;
    for (int i = 0; i < SCAN_PER; i++) {
        const int idx = base + i;
        if (idx < NNODES) {
            g_rowptr[idx] = off;
            g_cursor[idx] = off;
            off += g_count[idx];
        }
    }
    if (t == 1023) g_rowptr[NNODES] = sp[1023];
    if (t < 16) g_S[t] = 0.f;
}

// ---------------- K5: scatter edges dest-sorted + normalize + diversity sums ----------------
__global__ void __launch_bounds__(256) k_scatter(const int* __restrict__ ei) {
    __shared__ float red[8][10];
    const int e = blockIdx.x * 256 + threadIdx.x;
    float w0 = 0.f, w1 = 0.f, w2 = 0.f, w3 = 0.f;
    if (e < ET) {
        int r, c;
        if (e < E0) { r = ei[e]; c = ei[E0 + e]; } else { r = c = e - E0; }
        const float4 a   = g_alpha[e];
        const float4 den = *reinterpret_cast<const float4*>(g_denom + r * NH);
        w0 = a.x / (den.x + 1e-16f);
        w1 = a.y / (den.y + 1e-16f);
        w2 = a.z / (den.z + 1e-16f);
        w3 = a.w / (den.w + 1e-16f);
        const int pos = atomicAdd(&g_cursor[r], 1);
        g_scol[pos]   = c;
        g_salpha[pos] = make_float4(w0, w1, w2, w3);
    }
    float p[10];
    p[0] = w0 * w0; p[1] = w0 * w1; p[2] = w0 * w2; p[3] = w0 * w3;
    p[4] = w1 * w1; p[5] = w1 * w2; p[6] = w1 * w3;
    p[7] = w2 * w2; p[8] = w2 * w3; p[9] = w3 * w3;
#pragma unroll
    for (int i = 0; i < 10; i++)
#pragma unroll
        for (int o = 16; o > 0; o >>= 1)
            p[i] += __shfl_xor_sync(0xffffffffu, p[i], o);
    const int wid = threadIdx.x >> 5, lane = threadIdx.x & 31;
    if (lane == 0) {
#pragma unroll
        for (int i = 0; i < 10; i++) red[wid][i] = p[i];
    }
    __syncthreads();
    if (threadIdx.x < 10) {
        float s = 0.f;
#pragma unroll
        for (int k = 0; k < 8; k++) s += red[k][threadIdx.x];
        atomicAdd(&g_S[threadIdx.x], s);
    }
}

// ---------------- K6: CSR aggregation — warp per node, no atomics ----------------
__global__ void __launch_bounds__(256) k_agg(float* __restrict__ out,
                                             const float* __restrict__ bias) {
    const int n = (blockIdx.x * 256 + threadIdx.x) >> 5;
    if (n >= NNODES) return;
    const int lane = threadIdx.x & 31;
    const int beg = g_rowptr[n];
    const int end = g_rowptr[n + 1];
    const int h0 = lane >> 4;          // head of channel quad lane*4      (0 or 1)
    // second half channels 128+lane*4 -> head 2 or 3

    float4 acc0 = make_float4(0.f, 0.f, 0.f, 0.f);
    float4 acc1 = make_float4(0.f, 0.f, 0.f, 0.f);
    const float* sal = reinterpret_cast<const float*>(g_salpha);

    for (int j = beg; j < end; j++) {
        const int c = g_scol[j];
        const float w0 = sal[j * 4 + h0];
        const float w1 = sal[j * 4 + 2 + h0];
        const float4* row = reinterpret_cast<const float4*>(g_content + (size_t)c * HC);
        const float4 v0 = row[lane];
        const float4 v1 = row[32 + lane];
        acc0.x = fmaf(w0, v0.x, acc0.x); acc0.y = fmaf(w0, v0.y, acc0.y);
        acc0.z = fmaf(w0, v0.z, acc0.z); acc0.w = fmaf(w0, v0.w, acc0.w);
        acc1.x = fmaf(w1, v1.x, acc1.x); acc1.y = fmaf(w1, v1.y, acc1.y);
        acc1.z = fmaf(w1, v1.z, acc1.z); acc1.w = fmaf(w1, v1.w, acc1.w);
    }
    const float4 b0 = reinterpret_cast<const float4*>(bias)[lane];
    const float4 b1 = reinterpret_cast<const float4*>(bias)[32 + lane];
    float4* dst = reinterpret_cast<float4*>(out + (size_t)n * HC);
    dst[lane]      = make_float4(acc0.x + b0.x, acc0.y + b0.y, acc0.z + b0.z, acc0.w + b0.w);
    dst[32 + lane] = make_float4(acc1.x + b1.x, acc1.y + b1.y, acc1.z + b1.z, acc1.w + b1.w);
}

// ---------------- K7: diversity scalar ----------------
__global__ void k_finish(float* __restrict__ out, int outn) {
    if (blockIdx.x == 0 && threadIdx.x == 0) {
        const float n0 = fmaxf(sqrtf(g_S[0]), 1e-8f);
        const float n1 = fmaxf(sqrtf(g_S[4]), 1e-8f);
        const float n2 = fmaxf(sqrtf(g_S[7]), 1e-8f);
        const float n3 = fmaxf(sqrtf(g_S[9]), 1e-8f);
        float s = 0.f;
        s += 2.f * g_S[1] / (n0 * n1);
        s += 2.f * g_S[2] / (n0 * n2);
        s += 2.f * g_S[3] / (n0 * n3);
        s += 2.f * g_S[5] / (n1 * n2);
        s += 2.f * g_S[6] / (n1 * n3);
        s += 2.f * g_S[8] / (n2 * n3);
        out[outn] = (s / 16.f) * 0.1f;
    }
}

// ---------------- launch ----------------
extern "C" void kernel_launch(void* const* d_in, const int* in_sizes, int n_in,
                              void* d_out, int out_size) {
    const float* x    = (const float*)d_in[0];
    const int*   ei   = (const int*)d_in[1];
    const float* w    = (const float*)d_in[2];
    const float* att  = (const float*)d_in[3];
    const float* patt = (const float*)d_in[4];
    const float* bias = (const float*)d_in[5];
    float* out = (float*)d_out;
    const int outn = out_size - 1;

    static int smem_set = 0;
    if (!smem_set) {
        cudaFuncSetAttribute(k_gemm, cudaFuncAttributeMaxDynamicSharedMemorySize, SM_TOT);
        smem_set = 1;
    }

    dim3 ggrid((NNODES + TILE_M - 1) / TILE_M, HC / TILE_N);

    k_wsplit <<<(INC * HC + 255) / 256, 256>>>(w);
    k_gemm   <<<ggrid, 256, SM_TOT>>>(x);
    k_nodeatt<<<(NNODES * 32 + 255) / 256, 256>>>(x, att, patt);
    k_logexp <<<(ET + 255) / 256, 256>>>(ei);
    k_scan   <<<1, 1024>>>();
    k_scatter<<<(ET + 255) / 256, 256>>>(ei);
    k_agg    <<<(NNODES * 32 + 255) / 256, 256>>>(out, bias);
    k_finish <<<1, 32>>>(out, outn);
}

// round 11
// speedup vs baseline: 1.8447x; 1.0709x over previous
#include <cuda_runtime.h>
#include <cuda_bf16.h>
#include <cstdint>

#define NNODES 50000
#define XROW   272      // IN_CH + POS_DIM
#define INC    256
#define HC     256      // HEADS * OUT_CH
#define NH     4
#define E0     500000
#define ET     550000   // edges + self loops

// ---- GEMM tiling ----
#define TILE_M 128
#define TILE_N 128
#define KCHUNK 64
#define SROW   144
#define SM_AHI 0
#define SM_ALO (SM_AHI + TILE_M * SROW)
#define SM_BHI (SM_ALO + TILE_M * SROW)
#define SM_BLO (SM_BHI + TILE_N * SROW)
#define SM_TOT (SM_BLO + TILE_N * SROW)   // 73728

#define SCANB 49    // 49 * 1024 >= 50000

// ---------------- scratch (static device globals; no allocation) ----------------
__device__ __align__(16) float          g_content[(size_t)NNODES * HC]; // 51.2 MB
__device__ __align__(16) __nv_bfloat16  g_whi[INC * HC];
__device__ __align__(16) __nv_bfloat16  g_wlo[INC * HC];
__device__ __align__(16) float    g_u[8 * INC];         // W^T att (4 src + 4 dst)
__device__ __align__(16) float    g_s[NNODES * NH];
__device__ __align__(16) float    g_dv[NNODES * NH];
__device__ __align__(16) float    g_denom[NNODES * NH];
__device__ __align__(16) float4   g_alpha[ET];          // exp(logit)
__device__ __align__(16) float4   g_salpha[ET];         // normalized, dest-sorted
__device__             int        g_scol[ET];           // col index, dest-sorted
__device__             int        g_count[NNODES];
__device__             int        g_rowptr[NNODES + 1];
__device__             int        g_cursor[NNODES];
__device__             int        g_psum[SCANB];
__device__             int        g_poff[SCANB];
__device__             float      g_S[16];

// ---------------- helpers ----------------
__device__ __forceinline__ void red_add_v4(float* p, float a, float b, float c, float d) {
    asm volatile("red.global.add.v4.f32 [%0], {%1,%2,%3,%4};"
                 :: "l"(p), "f"(a), "f"(b), "f"(c), "f"(d) : "memory");
}
__device__ __forceinline__ void split8(const float* f, uint4& hi, uint4& lo) {
    float r[8];
    __nv_bfloat162 h01 = __floats2bfloat162_rn(f[0], f[1]);
    __nv_bfloat162 h23 = __floats2bfloat162_rn(f[2], f[3]);
    __nv_bfloat162 h45 = __floats2bfloat162_rn(f[4], f[5]);
    __nv_bfloat162 h67 = __floats2bfloat162_rn(f[6], f[7]);
    r[0] = f[0] - __bfloat162float(h01.x); r[1] = f[1] - __bfloat162float(h01.y);
    r[2] = f[2] - __bfloat162float(h23.x); r[3] = f[3] - __bfloat162float(h23.y);
    r[4] = f[4] - __bfloat162float(h45.x); r[5] = f[5] - __bfloat162float(h45.y);
    r[6] = f[6] - __bfloat162float(h67.x); r[7] = f[7] - __bfloat162float(h67.y);
    __nv_bfloat162 l01 = __floats2bfloat162_rn(r[0], r[1]);
    __nv_bfloat162 l23 = __floats2bfloat162_rn(r[2], r[3]);
    __nv_bfloat162 l45 = __floats2bfloat162_rn(r[4], r[5]);
    __nv_bfloat162 l67 = __floats2bfloat162_rn(r[6], r[7]);
    hi.x = *(uint32_t*)&h01; hi.y = *(uint32_t*)&h23; hi.z = *(uint32_t*)&h45; hi.w = *(uint32_t*)&h67;
    lo.x = *(uint32_t*)&l01; lo.y = *(uint32_t*)&l23; lo.z = *(uint32_t*)&l45; lo.w = *(uint32_t*)&l67;
}
__device__ __forceinline__ void mma16816(float* d, const uint32_t* a, const uint32_t* b) {
    asm volatile(
        "mma.sync.aligned.m16n8k16.row.col.f32.bf16.bf16.f32 "
        "{%0,%1,%2,%3}, {%4,%5,%6,%7}, {%8,%9}, {%0,%1,%2,%3};"
        : "+f"(d[0]), "+f"(d[1]), "+f"(d[2]), "+f"(d[3])
        : "r"(a[0]), "r"(a[1]), "r"(a[2]), "r"(a[3]), "r"(b[0]), "r"(b[1]));
}
__device__ __forceinline__ float dot4(float4 a, float4 b) {
    return fmaf(a.x, b.x, fmaf(a.y, b.y, fmaf(a.z, b.z, a.w * b.w)));
}

// ---------------- K0: split W into bf16 hi/lo planes ----------------
__global__ void k_wsplit(const float* __restrict__ w) {
    const int i = blockIdx.x * blockDim.x + threadIdx.x;
    if (i < INC * HC) {
        const float v = w[i];
        const __nv_bfloat16 h = __float2bfloat16_rn(v);
        g_whi[i] = h;
        g_wlo[i] = __float2bfloat16_rn(v - __bfloat162float(h));
    }
}

// ---------------- K1: content = x[:, :256] @ lin_w.T  (HMMA split-bf16) ----------------
__global__ void __launch_bounds__(256) k_gemm(const float* __restrict__ x) {
    extern __shared__ char sm[];
    const int tid  = threadIdx.x;
    const int wid  = tid >> 5;
    const int lane = tid & 31;
    const int m0   = blockIdx.x * TILE_M;
    const int nb   = blockIdx.y * TILE_N;
    const int mo   = (wid >> 1) * 32;
    const int no   = (wid & 1) * 64;
    const int g    = lane >> 2;
    const int c    = lane & 3;

    float acc[2][8][4];
#pragma unroll
    for (int mi = 0; mi < 2; mi++)
#pragma unroll
        for (int ni = 0; ni < 8; ni++)
#pragma unroll
            for (int q = 0; q < 4; q++) acc[mi][ni][q] = 0.f;

    for (int ch = 0; ch < INC / KCHUNK; ch++) {
        const int k0 = ch * KCHUNK;
        {
            const int r = tid >> 1;
            const int h = (tid & 1) * 32;
            const int n = m0 + r;
            float f[32];
            if (n < NNODES) {
                const float4* p = reinterpret_cast<const float4*>(x + (size_t)n * XROW + k0 + h);
#pragma unroll
                for (int j = 0; j < 8; j++) {
                    float4 v = p[j];
                    f[j * 4 + 0] = v.x; f[j * 4 + 1] = v.y; f[j * 4 + 2] = v.z; f[j * 4 + 3] = v.w;
                }
            } else {
#pragma unroll
                for (int j = 0; j < 32; j++) f[j] = 0.f;
            }
#pragma unroll
            for (int g4 = 0; g4 < 4; g4++) {
                uint4 hi, lo;
                split8(f + g4 * 8, hi, lo);
                const int off = r * SROW + (h + g4 * 8) * 2;
                *reinterpret_cast<uint4*>(sm + SM_AHI + off) = hi;
                *reinterpret_cast<uint4*>(sm + SM_ALO + off) = lo;
            }
        }
        {
            const int r = tid >> 1;
            const int h = (tid & 1) * 32;
            const uint4* ph = reinterpret_cast<const uint4*>(g_whi + (size_t)(nb + r) * INC + k0 + h);
            const uint4* pl = reinterpret_cast<const uint4*>(g_wlo + (size_t)(nb + r) * INC + k0 + h);
            const int off = r * SROW + h * 2;
#pragma unroll
            for (int j = 0; j < 4; j++) {
                *reinterpret_cast<uint4*>(sm + SM_BHI + off + j * 16) = ph[j];
                *reinterpret_cast<uint4*>(sm + SM_BLO + off + j * 16) = pl[j];
            }
        }
        __syncthreads();

#pragma unroll
        for (int ks = 0; ks < 4; ks++) {
            const int kb = ks * 32 + c * 4;
            uint32_t ah[2][4], al[2][4];
#pragma unroll
            for (int mi = 0; mi < 2; mi++) {
                const int base = (mo + mi * 16 + g) * SROW + kb;
                ah[mi][0] = *reinterpret_cast<const uint32_t*>(sm + SM_AHI + base);
                ah[mi][1] = *reinterpret_cast<const uint32_t*>(sm + SM_AHI + base + 8 * SROW);
                ah[mi][2] = *reinterpret_cast<const uint32_t*>(sm + SM_AHI + base + 16);
                ah[mi][3] = *reinterpret_cast<const uint32_t*>(sm + SM_AHI + base + 8 * SROW + 16);
                al[mi][0] = *reinterpret_cast<const uint32_t*>(sm + SM_ALO + base);
                al[mi][1] = *reinterpret_cast<const uint32_t*>(sm + SM_ALO + base + 8 * SROW);
                al[mi][2] = *reinterpret_cast<const uint32_t*>(sm + SM_ALO + base + 16);
                al[mi][3] = *reinterpret_cast<const uint32_t*>(sm + SM_ALO + base + 8 * SROW + 16);
            }
#pragma unroll
            for (int ni = 0; ni < 8; ni++) {
                const int bbase = (no + ni * 8 + g) * SROW + kb;
                uint32_t bh[2], bl[2];
                bh[0] = *reinterpret_cast<const uint32_t*>(sm + SM_BHI + bbase);
                bh[1] = *reinterpret_cast<const uint32_t*>(sm + SM_BHI + bbase + 16);
                bl[0] = *reinterpret_cast<const uint32_t*>(sm + SM_BLO + bbase);
                bl[1] = *reinterpret_cast<const uint32_t*>(sm + SM_BLO + bbase + 16);
                mma16816(acc[0][ni], ah[0], bh);
                mma16816(acc[1][ni], ah[1], bh);
                mma16816(acc[0][ni], ah[0], bl);
                mma16816(acc[1][ni], ah[1], bl);
                mma16816(acc[0][ni], al[0], bh);
                mma16816(acc[1][ni], al[1], bh);
            }
        }
        __syncthreads();
    }

#pragma unroll
    for (int mi = 0; mi < 2; mi++) {
        const int r0 = m0 + mo + mi * 16 + g;
        const int r1 = r0 + 8;
#pragma unroll
        for (int ni = 0; ni < 8; ni++) {
            const int col = nb + no + ni * 8 + c * 2;
            if (r0 < NNODES)
                *reinterpret_cast<float2*>(g_content + (size_t)r0 * HC + col) =
                    make_float2(acc[mi][ni][0], acc[mi][ni][1]);
            if (r1 < NNODES)
                *reinterpret_cast<float2*>(g_content + (size_t)r1 * HC + col) =
                    make_float2(acc[mi][ni][2], acc[mi][ni][3]);
        }
    }
}

// ---------------- K2a: u = W^T att (8 vectors of 256) ----------------
__global__ void __launch_bounds__(256) k_uatt(const float* __restrict__ w,
                                              const float* __restrict__ att) {
    const int k = threadIdx.x;
    float us[4] = {0.f, 0.f, 0.f, 0.f}, ud[4] = {0.f, 0.f, 0.f, 0.f};
#pragma unroll
    for (int h = 0; h < 4; h++) {
        for (int c = 0; c < 64; c++) {
            const float wv = w[(size_t)(h * 64 + c) * INC + k];
            us[h] = fmaf(att[h * 128 + c],      wv, us[h]);
            ud[h] = fmaf(att[h * 128 + 64 + c], wv, ud[h]);
        }
    }
#pragma unroll
    for (int h = 0; h < 4; h++) {
        g_u[h * INC + k]       = us[h];
        g_u[(4 + h) * INC + k] = ud[h];
    }
}

// ---------------- K2b: per-node logits from x directly; zero denom + counts ----------------
__global__ void __launch_bounds__(256) k_nodeatt(const float* __restrict__ x,
                                                 const float* __restrict__ patt) {
    const int gw   = (blockIdx.x * blockDim.x + threadIdx.x) >> 5;
    const int lane = threadIdx.x & 31;
    if (gw >= NNODES) return;
    const float4* xr = reinterpret_cast<const float4*>(x + (size_t)gw * XROW);
    const float4 xa = xr[lane];
    const float4 xb = xr[32 + lane];
    const float pv = (lane < 16) ? x[(size_t)gw * XROW + INC + lane] : 0.f;
#pragma unroll
    for (int h = 0; h < NH; h++) {
        const float4* us4 = reinterpret_cast<const float4*>(g_u + h * INC);
        const float4* ud4 = reinterpret_cast<const float4*>(g_u + (4 + h) * INC);
        float vs = dot4(xa, us4[lane]) + dot4(xb, us4[32 + lane]);
        float vd = dot4(xa, ud4[lane]) + dot4(xb, ud4[32 + lane]);
        if (lane < 16) {
            vs += pv * patt[h * 32 + lane];
            vd += pv * patt[h * 32 + 16 + lane];
        }
#pragma unroll
        for (int o = 16; o > 0; o >>= 1) {
            vs += __shfl_xor_sync(0xffffffffu, vs, o);
            vd += __shfl_xor_sync(0xffffffffu, vd, o);
        }
        if (lane == 0) { g_s[gw * NH + h] = vs; g_dv[gw * NH + h] = vd; }
    }
    if (lane < NH) g_denom[gw * NH + lane] = 0.f;
    if (lane == NH) g_count[gw] = 0;
}

// ---------------- K3: fused logits + leakyrelu + exp + denom + degree ----------------
__global__ void __launch_bounds__(256) k_logexp(const int* __restrict__ ei) {
    const int e = blockIdx.x * blockDim.x + threadIdx.x;
    if (e >= ET) return;
    int r, c;
    if (e < E0) { r = ei[e]; c = ei[E0 + e]; } else { r = c = e - E0; }
    const float4 sv = *reinterpret_cast<const float4*>(g_s  + r * NH);
    const float4 dv = *reinterpret_cast<const float4*>(g_dv + c * NH);
    float a0 = sv.x + dv.x, a1 = sv.y + dv.y, a2 = sv.z + dv.z, a3 = sv.w + dv.w;
    a0 = a0 > 0.f ? a0 : 0.2f * a0;
    a1 = a1 > 0.f ? a1 : 0.2f * a1;
    a2 = a2 > 0.f ? a2 : 0.2f * a2;
    a3 = a3 > 0.f ? a3 : 0.2f * a3;
    const float e0 = __expf(a0), e1 = __expf(a1), e2 = __expf(a2), e3 = __expf(a3);
    g_alpha[e] = make_float4(e0, e1, e2, e3);
    red_add_v4(g_denom + r * NH, e0, e1, e2, e3);
    atomicAdd(&g_count[r], 1);
}

// ---------------- K4a/b/c: coalesced 3-stage exclusive scan ----------------
__global__ void __launch_bounds__(1024) k_scan1() {
    __shared__ int sp[32];
    const int idx = blockIdx.x * 1024 + threadIdx.x;
    int v = (idx < NNODES) ? g_count[idx] : 0;
#pragma unroll
    for (int o = 16; o > 0; o >>= 1) v += __shfl_xor_sync(0xffffffffu, v, o);
    if ((threadIdx.x & 31) == 0) sp[threadIdx.x >> 5] = v;
    __syncthreads();
    if (threadIdx.x < 32) {
        int s = sp[threadIdx.x];
#pragma unroll
        for (int o = 16; o > 0; o >>= 1) s += __shfl_xor_sync(0xffffffffu, s, o);
        if (threadIdx.x == 0) g_psum[blockIdx.x] = s;
    }
}
__global__ void k_scan2() {
    const int t = threadIdx.x;   // 64 threads
    int v = (t < SCANB) ? g_psum[t] : 0;
    int acc = 0;
#pragma unroll
    for (int o = 1; o < 64; o <<= 1) {
        const int u = __shfl_up_sync(0xffffffffu, v, o, 32);
        if ((t & 31) >= o) v += u;
    }
    // two warps: warp1 needs warp0 total; do it simply with shared
    __shared__ int w0tot;
    if (t == 31) w0tot = v;
    __syncthreads();
    acc = (t >= 32) ? w0tot : 0;
    if (t < SCANB) g_poff[t] = v + acc - ((t < SCANB) ? g_psum[t] : 0); // exclusive
    if (t == 0) g_rowptr[NNODES] = ET;
    if (t < 16) g_S[t] = 0.f;
}
__global__ void __launch_bounds__(1024) k_scan3() {
    __shared__ int sw[32];
    const int idx = blockIdx.x * 1024 + threadIdx.x;
    const int lane = threadIdx.x & 31, wid = threadIdx.x >> 5;
    int v = (idx < NNODES) ? g_count[idx] : 0;
    const int mine = v;
    // warp inclusive scan
#pragma unroll
    for (int o = 1; o < 32; o <<= 1) {
        const int u = __shfl_up_sync(0xffffffffu, v, o);
        if (lane >= o) v += u;
    }
    if (lane == 31) sw[wid] = v;
    __syncthreads();
    if (wid == 0) {
        int s = (lane < 32) ? sw[lane] : 0;
#pragma unroll
        for (int o = 1; o < 32; o <<= 1) {
            const int u = __shfl_up_sync(0xffffffffu, s, o);
            if (lane >= o) s += u;
        }
        sw[lane] = s;
    }
    __syncthreads();
    const int warpoff = (wid > 0) ? sw[wid - 1] : 0;
    if (idx < NNODES) {
        const int excl = g_poff[blockIdx.x] + warpoff + v - mine;
        g_rowptr[idx] = excl;
        g_cursor[idx] = excl;
    }
}

// ---------------- K5: scatter edges dest-sorted + normalize + diversity sums ----------------
__global__ void __launch_bounds__(256) k_scatter(const int* __restrict__ ei) {
    __shared__ float red[8][10];
    const int e = blockIdx.x * 256 + threadIdx.x;
    float w0 = 0.f, w1 = 0.f, w2 = 0.f, w3 = 0.f;
    if (e < ET) {
        int r, c;
        if (e < E0) { r = ei[e]; c = ei[E0 + e]; } else { r = c = e - E0; }
        const float4 a   = g_alpha[e];
        const float4 den = *reinterpret_cast<const float4*>(g_denom + r * NH);
        w0 = a.x / (den.x + 1e-16f);
        w1 = a.y / (den.y + 1e-16f);
        w2 = a.z / (den.z + 1e-16f);
        w3 = a.w / (den.w + 1e-16f);
        const int pos = atomicAdd(&g_cursor[r], 1);
        g_scol[pos]   = c;
        g_salpha[pos] = make_float4(w0, w1, w2, w3);
    }
    float p[10];
    p[0] = w0 * w0; p[1] = w0 * w1; p[2] = w0 * w2; p[3] = w0 * w3;
    p[4] = w1 * w1; p[5] = w1 * w2; p[6] = w1 * w3;
    p[7] = w2 * w2; p[8] = w2 * w3; p[9] = w3 * w3;
#pragma unroll
    for (int i = 0; i < 10; i++)
#pragma unroll
        for (int o = 16; o > 0; o >>= 1)
            p[i] += __shfl_xor_sync(0xffffffffu, p[i], o);
    const int wid = threadIdx.x >> 5, lane = threadIdx.x & 31;
    if (lane == 0) {
#pragma unroll
        for (int i = 0; i < 10; i++) red[wid][i] = p[i];
    }
    __syncthreads();
    if (threadIdx.x < 10) {
        float s = 0.f;
#pragma unroll
        for (int k = 0; k < 8; k++) s += red[k][threadIdx.x];
        atomicAdd(&g_S[threadIdx.x], s);
    }
}

// ---------------- K6: CSR aggregation — 2 warps/node, batched col prefetch ----------------
__global__ void __launch_bounds__(256) k_agg(float* __restrict__ out,
                                             const float* __restrict__ bias) {
    const int gw = (blockIdx.x * 256 + threadIdx.x) >> 5;
    const int n = gw >> 1;
    if (n >= NNODES) return;
    const int half = gw & 1;
    const int lane = threadIdx.x & 31;
    const int beg = g_rowptr[n];
    const int end = g_rowptr[n + 1];
    const int head = half * 2 + (lane >> 4);
    const int coff = half * 32 + lane;       // float4 index within row
    const float* sal = reinterpret_cast<const float*>(g_salpha);

    float4 acc = make_float4(0.f, 0.f, 0.f, 0.f);
    for (int base = beg; base < end; base += 8) {
        const int myj = base + (lane & 7);
        const int mycol = (myj < end) ? g_scol[myj] : -1;
#pragma unroll
        for (int t = 0; t < 8; t++) {
            const int c = __shfl_sync(0xffffffffu, mycol, t);
            if (c >= 0) {
                const float wv = sal[(size_t)(base + t) * 4 + head];
                const float4 v = reinterpret_cast<const float4*>(g_content + (size_t)c * HC)[coff];
                acc.x = fmaf(wv, v.x, acc.x);
                acc.y = fmaf(wv, v.y, acc.y);
                acc.z = fmaf(wv, v.z, acc.z);
                acc.w = fmaf(wv, v.w, acc.w);
            }
        }
    }
    const float4 b = reinterpret_cast<const float4*>(bias)[coff];
    reinterpret_cast<float4*>(out + (size_t)n * HC)[coff] =
        make_float4(acc.x + b.x, acc.y + b.y, acc.z + b.z, acc.w + b.w);
}

// ---------------- K7: diversity scalar ----------------
__global__ void k_finish(float* __restrict__ out, int outn) {
    if (blockIdx.x == 0 && threadIdx.x == 0) {
        const float n0 = fmaxf(sqrtf(g_S[0]), 1e-8f);
        const float n1 = fmaxf(sqrtf(g_S[4]), 1e-8f);
        const float n2 = fmaxf(sqrtf(g_S[7]), 1e-8f);
        const float n3 = fmaxf(sqrtf(g_S[9]), 1e-8f);
        float s = 0.f;
        s += 2.f * g_S[1] / (n0 * n1);
        s += 2.f * g_S[2] / (n0 * n2);
        s += 2.f * g_S[3] / (n0 * n3);
        s += 2.f * g_S[5] / (n1 * n2);
        s += 2.f * g_S[6] / (n1 * n3);
        s += 2.f * g_S[8] / (n2 * n3);
        out[outn] = (s / 16.f) * 0.1f;
    }
}

// ---------------- launch ----------------
extern "C" void kernel_launch(void* const* d_in, const int* in_sizes, int n_in,
                              void* d_out, int out_size) {
    const float* x    = (const float*)d_in[0];
    const int*   ei   = (const int*)d_in[1];
    const float* w    = (const float*)d_in[2];
    const float* att  = (const float*)d_in[3];
    const float* patt = (const float*)d_in[4];
    const float* bias = (const float*)d_in[5];
    float* out = (float*)d_out;
    const int outn = out_size - 1;

    static int smem_set = 0;
    if (!smem_set) {
        cudaFuncSetAttribute(k_gemm, cudaFuncAttributeMaxDynamicSharedMemorySize, SM_TOT);
        smem_set = 1;
    }

    dim3 ggrid((NNODES + TILE_M - 1) / TILE_M, HC / TILE_N);

    k_wsplit <<<(INC * HC + 255) / 256, 256>>>(w);
    k_gemm   <<<ggrid, 256, SM_TOT>>>(x);
    k_uatt   <<<1, 256>>>(w, att);
    k_nodeatt<<<(NNODES * 32 + 255) / 256, 256>>>(x, patt);
    k_logexp <<<(ET + 255) / 256, 256>>>(ei);
    k_scan1  <<<SCANB, 1024>>>();
    k_scan2  <<<1, 64>>>();
    k_scan3  <<<SCANB, 1024>>>();
    k_scatter<<<(ET + 255) / 256, 256>>>(ei);
    k_agg    <<<(NNODES * 2 * 32 + 255) / 256, 256>>>(out, bias);
    k_finish <<<1, 32>>>(out, outn);
}

// round 14
// speedup vs baseline: 2.1810x; 1.1823x over previous
#include <cuda_runtime.h>
#include <cuda_bf16.h>
#include <cstdint>

#define NNODES 50000
#define XROW   272      // IN_CH + POS_DIM
#define INC    256
#define HC     256      // HEADS * OUT_CH
#define NH     4
#define E0     500000
#define ET     550000   // edges + self loops

// ---- GEMM tiling ----
#define TILE_M 128
#define TILE_N 128
#define KCHUNK 64
#define SROW   144
#define SM_AHI 0
#define SM_ALO (SM_AHI + TILE_M * SROW)
#define SM_BHI (SM_ALO + TILE_M * SROW)
#define SM_BLO (SM_BHI + TILE_N * SROW)
#define SM_TOT (SM_BLO + TILE_N * SROW)   // 73728

#define SCANB 49    // 49 * 1024 >= 50000

// ---------------- scratch (static device globals; no allocation) ----------------
__device__ __align__(16) float          g_content[(size_t)NNODES * HC]; // 51.2 MB
__device__ __align__(16) __nv_bfloat16  g_whi[INC * HC];
__device__ __align__(16) __nv_bfloat16  g_wlo[INC * HC];
__device__ __align__(16) float    g_s[NNODES * NH];
__device__ __align__(16) float    g_dv[NNODES * NH];
__device__ __align__(16) float    g_denom[NNODES * NH];
__device__ __align__(16) float4   g_alpha[ET];          // exp(logit)
__device__ __align__(16) float4   g_salpha[ET];         // normalized, dest-sorted
__device__             int        g_scol[ET];           // col index, dest-sorted
__device__             int        g_count[NNODES];
__device__             int        g_rowptr[NNODES + 1];
__device__             int        g_cursor[NNODES];
__device__             int        g_psum[SCANB];
__device__             int        g_poff[SCANB];
__device__             float      g_S[16];

// ---------------- helpers ----------------
__device__ __forceinline__ void red_add_v4(float* p, float a, float b, float c, float d) {
    asm volatile("red.global.add.v4.f32 [%0], {%1,%2,%3,%4};"
                 :: "l"(p), "f"(a), "f"(b), "f"(c), "f"(d) : "memory");
}
__device__ __forceinline__ void red_add_f32(float* p, float a) {
    asm volatile("red.global.add.f32 [%0], %1;" :: "l"(p), "f"(a) : "memory");
}
__device__ __forceinline__ void split8(const float* f, uint4& hi, uint4& lo) {
    float r[8];
    __nv_bfloat162 h01 = __floats2bfloat162_rn(f[0], f[1]);
    __nv_bfloat162 h23 = __floats2bfloat162_rn(f[2], f[3]);
    __nv_bfloat162 h45 = __floats2bfloat162_rn(f[4], f[5]);
    __nv_bfloat162 h67 = __floats2bfloat162_rn(f[6], f[7]);
    r[0] = f[0] - __bfloat162float(h01.x); r[1] = f[1] - __bfloat162float(h01.y);
    r[2] = f[2] - __bfloat162float(h23.x); r[3] = f[3] - __bfloat162float(h23.y);
    r[4] = f[4] - __bfloat162float(h45.x); r[5] = f[5] - __bfloat162float(h45.y);
    r[6] = f[6] - __bfloat162float(h67.x); r[7] = f[7] - __bfloat162float(h67.y);
    __nv_bfloat162 l01 = __floats2bfloat162_rn(r[0], r[1]);
    __nv_bfloat162 l23 = __floats2bfloat162_rn(r[2], r[3]);
    __nv_bfloat162 l45 = __floats2bfloat162_rn(r[4], r[5]);
    __nv_bfloat162 l67 = __floats2bfloat162_rn(r[6], r[7]);
    hi.x = *(uint32_t*)&h01; hi.y = *(uint32_t*)&h23; hi.z = *(uint32_t*)&h45; hi.w = *(uint32_t*)&h67;
    lo.x = *(uint32_t*)&l01; lo.y = *(uint32_t*)&l23; lo.z = *(uint32_t*)&l45; lo.w = *(uint32_t*)&l67;
}
__device__ __forceinline__ void mma16816(float* d, const uint32_t* a, const uint32_t* b) {
    asm volatile(
        "mma.sync.aligned.m16n8k16.row.col.f32.bf16.bf16.f32 "
        "{%0,%1,%2,%3}, {%4,%5,%6,%7}, {%8,%9}, {%0,%1,%2,%3};"
        : "+f"(d[0]), "+f"(d[1]), "+f"(d[2]), "+f"(d[3])
        : "r"(a[0]), "r"(a[1]), "r"(a[2]), "r"(a[3]), "r"(b[0]), "r"(b[1]));
}

// ---------------- K0: split W into bf16 hi/lo planes ----------------
__global__ void k_wsplit(const float* __restrict__ w) {
    const int i = blockIdx.x * blockDim.x + threadIdx.x;
    if (i < INC * HC) {
        const float v = w[i];
        const __nv_bfloat16 h = __float2bfloat16_rn(v);
        g_whi[i] = h;
        g_wlo[i] = __float2bfloat16_rn(v - __bfloat162float(h));
    }
}

// ---------------- K0b: pos logits seed g_s/g_dv; zero denom + counts ----------------
__global__ void __launch_bounds__(256) k_pos(const float* __restrict__ x,
                                             const float* __restrict__ patt) {
    const int gw   = (blockIdx.x * blockDim.x + threadIdx.x) >> 5;
    const int lane = threadIdx.x & 31;
    if (gw >= NNODES) return;
    const float pv = (lane < 16) ? x[(size_t)gw * XROW + INC + lane] : 0.f;
#pragma unroll
    for (int h = 0; h < NH; h++) {
        float vs = 0.f, vd = 0.f;
        if (lane < 16) {
            vs = pv * patt[h * 32 + lane];
            vd = pv * patt[h * 32 + 16 + lane];
        }
#pragma unroll
        for (int o = 8; o > 0; o >>= 1) {
            vs += __shfl_xor_sync(0xffffffffu, vs, o);
            vd += __shfl_xor_sync(0xffffffffu, vd, o);
        }
        if (lane == 0) { g_s[gw * NH + h] = vs; g_dv[gw * NH + h] = vd; }
    }
    if (lane < NH) g_denom[gw * NH + lane] = 0.f;
    if (lane == NH) g_count[gw] = 0;
}

// ---------------- K1: content = x @ W^T (HMMA split-bf16) + fused attention logits ----------------
__global__ void __launch_bounds__(256) k_gemm(const float* __restrict__ x,
                                              const float* __restrict__ att) {
    extern __shared__ char sm[];
    const int tid  = threadIdx.x;
    const int wid  = tid >> 5;
    const int lane = tid & 31;
    const int m0   = blockIdx.x * TILE_M;
    const int nb   = blockIdx.y * TILE_N;
    const int mo   = (wid >> 1) * 32;
    const int no   = (wid & 1) * 64;
    const int g    = lane >> 2;
    const int c    = lane & 3;

    float acc[2][8][4];
#pragma unroll
    for (int mi = 0; mi < 2; mi++)
#pragma unroll
        for (int ni = 0; ni < 8; ni++)
#pragma unroll
            for (int q = 0; q < 4; q++) acc[mi][ni][q] = 0.f;

    for (int ch = 0; ch < INC / KCHUNK; ch++) {
        const int k0 = ch * KCHUNK;
        {
            const int r = tid >> 1;
            const int h = (tid & 1) * 32;
            const int n = m0 + r;
            float f[32];
            if (n < NNODES) {
                const float4* p = reinterpret_cast<const float4*>(x + (size_t)n * XROW + k0 + h);
#pragma unroll
                for (int j = 0; j < 8; j++) {
                    float4 v = p[j];
                    f[j * 4 + 0] = v.x; f[j * 4 + 1] = v.y; f[j * 4 + 2] = v.z; f[j * 4 + 3] = v.w;
                }
            } else {
#pragma unroll
                for (int j = 0; j < 32; j++) f[j] = 0.f;
            }
#pragma unroll
            for (int g4 = 0; g4 < 4; g4++) {
                uint4 hi, lo;
                split8(f + g4 * 8, hi, lo);
                const int off = r * SROW + (h + g4 * 8) * 2;
                *reinterpret_cast<uint4*>(sm + SM_AHI + off) = hi;
                *reinterpret_cast<uint4*>(sm + SM_ALO + off) = lo;
            }
        }
        {
            const int r = tid >> 1;
            const int h = (tid & 1) * 32;
            const uint4* ph = reinterpret_cast<const uint4*>(g_whi + (size_t)(nb + r) * INC + k0 + h);
            const uint4* pl = reinterpret_cast<const uint4*>(g_wlo + (size_t)(nb + r) * INC + k0 + h);
            const int off = r * SROW + h * 2;
#pragma unroll
            for (int j = 0; j < 4; j++) {
                *reinterpret_cast<uint4*>(sm + SM_BHI + off + j * 16) = ph[j];
                *reinterpret_cast<uint4*>(sm + SM_BLO + off + j * 16) = pl[j];
            }
        }
        __syncthreads();

#pragma unroll
        for (int ks = 0; ks < 4; ks++) {
            const int kb = ks * 32 + c * 4;
            uint32_t ah[2][4], al[2][4];
#pragma unroll
            for (int mi = 0; mi < 2; mi++) {
                const int base = (mo + mi * 16 + g) * SROW + kb;
                ah[mi][0] = *reinterpret_cast<const uint32_t*>(sm + SM_AHI + base);
                ah[mi][1] = *reinterpret_cast<const uint32_t*>(sm + SM_AHI + base + 8 * SROW);
                ah[mi][2] = *reinterpret_cast<const uint32_t*>(sm + SM_AHI + base + 16);
                ah[mi][3] = *reinterpret_cast<const uint32_t*>(sm + SM_AHI + base + 8 * SROW + 16);
                al[mi][0] = *reinterpret_cast<const uint32_t*>(sm + SM_ALO + base);
                al[mi][1] = *reinterpret_cast<const uint32_t*>(sm + SM_ALO + base + 8 * SROW);
                al[mi][2] = *reinterpret_cast<const uint32_t*>(sm + SM_ALO + base + 16);
                al[mi][3] = *reinterpret_cast<const uint32_t*>(sm + SM_ALO + base + 8 * SROW + 16);
            }
#pragma unroll
            for (int ni = 0; ni < 8; ni++) {
                const int bbase = (no + ni * 8 + g) * SROW + kb;
                uint32_t bh[2], bl[2];
                bh[0] = *reinterpret_cast<const uint32_t*>(sm + SM_BHI + bbase);
                bh[1] = *reinterpret_cast<const uint32_t*>(sm + SM_BHI + bbase + 16);
                bl[0] = *reinterpret_cast<const uint32_t*>(sm + SM_BLO + bbase);
                bl[1] = *reinterpret_cast<const uint32_t*>(sm + SM_BLO + bbase + 16);
                mma16816(acc[0][ni], ah[0], bh);
                mma16816(acc[1][ni], ah[1], bh);
                mma16816(acc[0][ni], ah[0], bl);
                mma16816(acc[1][ni], ah[1], bl);
                mma16816(acc[0][ni], al[0], bh);
                mma16816(acc[1][ni], al[1], bh);
            }
        }
        __syncthreads();
    }

    // ---- epilogue 1: store content ----
#pragma unroll
    for (int mi = 0; mi < 2; mi++) {
        const int r0 = m0 + mo + mi * 16 + g;
        const int r1 = r0 + 8;
#pragma unroll
        for (int ni = 0; ni < 8; ni++) {
            const int col = nb + no + ni * 8 + c * 2;
            if (r0 < NNODES)
                *reinterpret_cast<float2*>(g_content + (size_t)r0 * HC + col) =
                    make_float2(acc[mi][ni][0], acc[mi][ni][1]);
            if (r1 < NNODES)
                *reinterpret_cast<float2*>(g_content + (size_t)r1 * HC + col) =
                    make_float2(acc[mi][ni][2], acc[mi][ni][3]);
        }
    }

    // ---- epilogue 2: fused attention logits (this warp owns full head h) ----
    const int h = (nb + no) >> 6;          // head index 0..3
    float as[16], ad[16];
#pragma unroll
    for (int ni = 0; ni < 8; ni++) {
#pragma unroll
        for (int q = 0; q < 2; q++) {
            const int ci = ni * 8 + c * 2 + q;
            as[ni * 2 + q] = att[h * 128 + ci];
            ad[ni * 2 + q] = att[h * 128 + 64 + ci];
        }
    }
#pragma unroll
    for (int mi = 0; mi < 2; mi++) {
        float vs0 = 0.f, vd0 = 0.f, vs1 = 0.f, vd1 = 0.f;
#pragma unroll
        for (int ni = 0; ni < 8; ni++) {
            vs0 = fmaf(acc[mi][ni][0], as[ni * 2], fmaf(acc[mi][ni][1], as[ni * 2 + 1], vs0));
            vd0 = fmaf(acc[mi][ni][0], ad[ni * 2], fmaf(acc[mi][ni][1], ad[ni * 2 + 1], vd0));
            vs1 = fmaf(acc[mi][ni][2], as[ni * 2], fmaf(acc[mi][ni][3], as[ni * 2 + 1], vs1));
            vd1 = fmaf(acc[mi][ni][2], ad[ni * 2], fmaf(acc[mi][ni][3], ad[ni * 2 + 1], vd1));
        }
#pragma unroll
        for (int o = 1; o <= 2; o <<= 1) {
            vs0 += __shfl_xor_sync(0xffffffffu, vs0, o);
            vd0 += __shfl_xor_sync(0xffffffffu, vd0, o);
            vs1 += __shfl_xor_sync(0xffffffffu, vs1, o);
            vd1 += __shfl_xor_sync(0xffffffffu, vd1, o);
        }
        if (c == 0) {
            const int r0 = m0 + mo + mi * 16 + g;
            const int r1 = r0 + 8;
            if (r0 < NNODES) {
                red_add_f32(g_s  + r0 * NH + h, vs0);
                red_add_f32(g_dv + r0 * NH + h, vd0);
            }
            if (r1 < NNODES) {
                red_add_f32(g_s  + r1 * NH + h, vs1);
                red_add_f32(g_dv + r1 * NH + h, vd1);
            }
        }
    }
}

// ---------------- K3: fused logits + leakyrelu + exp + denom + degree ----------------
__global__ void __launch_bounds__(256) k_logexp(const int* __restrict__ ei) {
    const int e = blockIdx.x * blockDim.x + threadIdx.x;
    if (e >= ET) return;
    int r, c;
    if (e < E0) { r = ei[e]; c = ei[E0 + e]; } else { r = c = e - E0; }
    const float4 sv = *reinterpret_cast<const float4*>(g_s  + r * NH);
    const float4 dv = *reinterpret_cast<const float4*>(g_dv + c * NH);
    float a0 = sv.x + dv.x, a1 = sv.y + dv.y, a2 = sv.z + dv.z, a3 = sv.w + dv.w;
    a0 = a0 > 0.f ? a0 : 0.2f * a0;
    a1 = a1 > 0.f ? a1 : 0.2f * a1;
    a2 = a2 > 0.f ? a2 : 0.2f * a2;
    a3 = a3 > 0.f ? a3 : 0.2f * a3;
    const float e0 = __expf(a0), e1 = __expf(a1), e2 = __expf(a2), e3 = __expf(a3);
    g_alpha[e] = make_float4(e0, e1, e2, e3);
    red_add_v4(g_denom + r * NH, e0, e1, e2, e3);
    atomicAdd(&g_count[r], 1);
}

// ---------------- K4a/b/c: coalesced 3-stage exclusive scan ----------------
__global__ void __launch_bounds__(1024) k_scan1() {
    __shared__ int sp[32];
    const int idx = blockIdx.x * 1024 + threadIdx.x;
    int v = (idx < NNODES) ? g_count[idx] : 0;
#pragma unroll
    for (int o = 16; o > 0; o >>= 1) v += __shfl_xor_sync(0xffffffffu, v, o);
    if ((threadIdx.x & 31) == 0) sp[threadIdx.x >> 5] = v;
    __syncthreads();
    if (threadIdx.x < 32) {
        int s = sp[threadIdx.x];
#pragma unroll
        for (int o = 16; o > 0; o >>= 1) s += __shfl_xor_sync(0xffffffffu, s, o);
        if (threadIdx.x == 0) g_psum[blockIdx.x] = s;
    }
}
__global__ void k_scan2() {
    const int t = threadIdx.x;   // 64 threads
    int v = (t < SCANB) ? g_psum[t] : 0;
    int acc = 0;
#pragma unroll
    for (int o = 1; o < 64; o <<= 1) {
        const int u = __shfl_up_sync(0xffffffffu, v, o, 32);
        if ((t & 31) >= o) v += u;
    }
    __shared__ int w0tot;
    if (t == 31) w0tot = v;
    __syncthreads();
    acc = (t >= 32) ? w0tot : 0;
    if (t < SCANB) g_poff[t] = v + acc - g_psum[t]; // exclusive
    if (t == 0) g_rowptr[NNODES] = ET;
    if (t < 16) g_S[t] = 0.f;
}
__global__ void __launch_bounds__(1024) k_scan3() {
    __shared__ int sw[32];
    const int idx = blockIdx.x * 1024 + threadIdx.x;
    const int lane = threadIdx.x & 31, wid = threadIdx.x >> 5;
    int v = (idx < NNODES) ? g_count[idx] : 0;
    const int mine = v;
#pragma unroll
    for (int o = 1; o < 32; o <<= 1) {
        const int u = __shfl_up_sync(0xffffffffu, v, o);
        if (lane >= o) v += u;
    }
    if (lane == 31) sw[wid] = v;
    __syncthreads();
    if (wid == 0) {
        int s = sw[lane];
#pragma unroll
        for (int o = 1; o < 32; o <<= 1) {
            const int u = __shfl_up_sync(0xffffffffu, s, o);
            if (lane >= o) s += u;
        }
        sw[lane] = s;
    }
    __syncthreads();
    const int warpoff = (wid > 0) ? sw[wid - 1] : 0;
    if (idx < NNODES) {
        const int excl = g_poff[blockIdx.x] + warpoff + v - mine;
        g_rowptr[idx] = excl;
        g_cursor[idx] = excl;
    }
}

// ---------------- K5: scatter edges dest-sorted + normalize + diversity sums ----------------
__global__ void __launch_bounds__(256) k_scatter(const int* __restrict__ ei) {
    __shared__ float red[8][10];
    const int e = blockIdx.x * 256 + threadIdx.x;
    float w0 = 0.f, w1 = 0.f, w2 = 0.f, w3 = 0.f;
    if (e < ET) {
        int r, c;
        if (e < E0) { r = ei[e]; c = ei[E0 + e]; } else { r = c = e - E0; }
        const float4 a   = g_alpha[e];
        const float4 den = *reinterpret_cast<const float4*>(g_denom + r * NH);
        w0 = a.x / (den.x + 1e-16f);
        w1 = a.y / (den.y + 1e-16f);
        w2 = a.z / (den.z + 1e-16f);
        w3 = a.w / (den.w + 1e-16f);
        const int pos = atomicAdd(&g_cursor[r], 1);
        g_scol[pos]   = c;
        g_salpha[pos] = make_float4(w0, w1, w2, w3);
    }
    float p[10];
    p[0] = w0 * w0; p[1] = w0 * w1; p[2] = w0 * w2; p[3] = w0 * w3;
    p[4] = w1 * w1; p[5] = w1 * w2; p[6] = w1 * w3;
    p[7] = w2 * w2; p[8] = w2 * w3; p[9] = w3 * w3;
#pragma unroll
    for (int i = 0; i < 10; i++)
#pragma unroll
        for (int o = 16; o > 0; o >>= 1)
            p[i] += __shfl_xor_sync(0xffffffffu, p[i], o);
    const int wid = threadIdx.x >> 5, lane = threadIdx.x & 31;
    if (lane == 0) {
#pragma unroll
        for (int i = 0; i < 10; i++) red[wid][i] = p[i];
    }
    __syncthreads();
    if (threadIdx.x < 10) {
        float s = 0.f;
#pragma unroll
        for (int k = 0; k < 8; k++) s += red[k][threadIdx.x];
        atomicAdd(&g_S[threadIdx.x], s);
    }
}

// ---------------- K6: CSR aggregation — 2 warps/node, batched col prefetch ----------------
__global__ void __launch_bounds__(256) k_agg(float* __restrict__ out,
                                             const float* __restrict__ bias) {
    const int gw = (blockIdx.x * 256 + threadIdx.x) >> 5;
    const int n = gw >> 1;
    if (n >= NNODES) return;
    const int half = gw & 1;
    const int lane = threadIdx.x & 31;
    const int beg = g_rowptr[n];
    const int end = g_rowptr[n + 1];
    const int head = half * 2 + (lane >> 4);
    const int coff = half * 32 + lane;       // float4 index within row
    const float* sal = reinterpret_cast<const float*>(g_salpha);

    float4 acc = make_float4(0.f, 0.f, 0.f, 0.f);
    for (int base = beg; base < end; base += 8) {
        const int myj = base + (lane & 7);
        const int mycol = (myj < end) ? g_scol[myj] : -1;
#pragma unroll
        for (int t = 0; t < 8; t++) {
            const int c = __shfl_sync(0xffffffffu, mycol, t);
            if (c >= 0) {
                const float wv = sal[(size_t)(base + t) * 4 + head];
                const float4 v = reinterpret_cast<const float4*>(g_content + (size_t)c * HC)[coff];
                acc.x = fmaf(wv, v.x, acc.x);
                acc.y = fmaf(wv, v.y, acc.y);
                acc.z = fmaf(wv, v.z, acc.z);
                acc.w = fmaf(wv, v.w, acc.w);
            }
        }
    }
    const float4 b = reinterpret_cast<const float4*>(bias)[coff];
    reinterpret_cast<float4*>(out + (size_t)n * HC)[coff] =
        make_float4(acc.x + b.x, acc.y + b.y, acc.z + b.z, acc.w + b.w);
}

// ---------------- K7: diversity scalar ----------------
__global__ void k_finish(float* __restrict__ out, int outn) {
    if (blockIdx.x == 0 && threadIdx.x == 0) {
        const float n0 = fmaxf(sqrtf(g_S[0]), 1e-8f);
        const float n1 = fmaxf(sqrtf(g_S[4]), 1e-8f);
        const float n2 = fmaxf(sqrtf(g_S[7]), 1e-8f);
        const float n3 = fmaxf(sqrtf(g_S[9]), 1e-8f);
        float s = 0.f;
        s += 2.f * g_S[1] / (n0 * n1);
        s += 2.f * g_S[2] / (n0 * n2);
        s += 2.f * g_S[3] / (n0 * n3);
        s += 2.f * g_S[5] / (n1 * n2);
        s += 2.f * g_S[6] / (n1 * n3);
        s += 2.f * g_S[8] / (n2 * n3);
        out[outn] = (s / 16.f) * 0.1f;
    }
}

// ---------------- launch ----------------
extern "C" void kernel_launch(void* const* d_in, const int* in_sizes, int n_in,
                              void* d_out, int out_size) {
    const float* x    = (const float*)d_in[0];
    const int*   ei   = (const int*)d_in[1];
    const float* w    = (const float*)d_in[2];
    const float* att  = (const float*)d_in[3];
    const float* patt = (const float*)d_in[4];
    const float* bias = (const float*)d_in[5];
    float* out = (float*)d_out;
    const int outn = out_size - 1;

    static int smem_set = 0;
    if (!smem_set) {
        cudaFuncSetAttribute(k_gemm, cudaFuncAttributeMaxDynamicSharedMemorySize, SM_TOT);
        smem_set = 1;
    }

    dim3 ggrid((NNODES + TILE_M - 1) / TILE_M, HC / TILE_N);

    k_wsplit <<<(INC * HC + 255) / 256, 256>>>(w);
    k_pos    <<<(NNODES * 32 + 255) / 256, 256>>>(x, patt);
    k_gemm   <<<ggrid, 256, SM_TOT>>>(x, att);
    k_logexp <<<(ET + 255) / 256, 256>>>(ei);
    k_scan1  <<<SCANB, 1024>>>();
    k_scan2  <<<1, 64>>>();
    k_scan3  <<<SCANB, 1024>>>();
    k_scatter<<<(ET + 255) / 256, 256>>>(ei);
    k_agg    <<<(NNODES * 2 * 32 + 255) / 256, 256>>>(out, bias);
    k_finish <<<1, 32>>>(out, outn);
}